// round 1
// baseline (speedup 1.0000x reference)
#include <cuda_runtime.h>

#define NN 100000
#define EE 1600000

// ---------------- scratch (static device globals; no allocation) ------------
__device__ float g_hp1[NN * 64];
__device__ float g_out1[NN * 64];
__device__ float g_as1[NN * 4];
__device__ float g_ad1[NN * 4];
__device__ float g_amax1[NN * 4];
__device__ float g_asum1[NN * 4];
__device__ float g_hp2[NN * 64];
__device__ float g_out2[NN * 64];
__device__ float g_as2[NN];
__device__ float g_ad2[NN];
__device__ float g_amax2[NN];
__device__ float g_asum2[NN];
__device__ float g_h2[NN * 64];
__device__ float g_EA[NN * 64];
__device__ float g_EB[NN * 64];

// ---------------- helpers ---------------------------------------------------
__device__ __forceinline__ float lrelu(float x, float s) { return x > 0.f ? x : s * x; }

// float atomic max via monotonic int mapping (no NaNs in this workload)
__device__ __forceinline__ void atomicMaxF(float* a, float v) {
    if (v >= 0.f) atomicMax((int*)a, __float_as_int(v));
    else          atomicMin((unsigned int*)a, __float_as_uint(v));
}

// vector reduction-add (sm_90+): 1 instruction scatters 16B
__device__ __forceinline__ void red4(float* a, float x, float y, float z, float w) {
    asm volatile("red.global.add.v4.f32 [%0], {%1,%2,%3,%4};"
                 :: "l"(a), "f"(x), "f"(y), "f"(z), "f"(w) : "memory");
}

// ---------------- kernel 1: encoder + gat1 projection + alpha pre -----------
__global__ void k_enc_gat1(const float* __restrict__ x,
                           const float* __restrict__ encW, const float* __restrict__ encb,
                           const float* __restrict__ g1W,
                           const float* __restrict__ g1as, const float* __restrict__ g1ad,
                           int n) {
    __shared__ __align__(16) float sW[64 * 64];
    __shared__ __align__(16) float sEnc[128];
    __shared__ __align__(16) float sEb[64], sAs[64], sAd[64];
    for (int i = threadIdx.x; i < 4096; i += blockDim.x) sW[i] = g1W[i];
    if (threadIdx.x < 128) sEnc[threadIdx.x] = encW[threadIdx.x];
    if (threadIdx.x < 64) {
        sEb[threadIdx.x] = encb[threadIdx.x];
        sAs[threadIdx.x] = g1as[threadIdx.x];
        sAd[threadIdx.x] = g1ad[threadIdx.x];
    }
    __syncthreads();
    int node = blockIdx.x * blockDim.x + threadIdx.x;
    if (node >= n) return;

    float x0 = x[node * 2], x1 = x[node * 2 + 1];
    float h0[64];
#pragma unroll
    for (int k = 0; k < 64; k++)
        h0[k] = fmaf(x0, sEnc[k], fmaf(x1, sEnc[64 + k], sEb[k]));

    float asv[4] = {0, 0, 0, 0}, adv[4] = {0, 0, 0, 0};
    for (int c4 = 0; c4 < 16; c4++) {
        float ax = 0, ay = 0, az = 0, aw = 0;
#pragma unroll
        for (int k = 0; k < 64; k++) {
            float4 w = *(const float4*)&sW[k * 64 + c4 * 4];
            ax = fmaf(h0[k], w.x, ax);
            ay = fmaf(h0[k], w.y, ay);
            az = fmaf(h0[k], w.z, az);
            aw = fmaf(h0[k], w.w, aw);
        }
        float4 o = make_float4(ax, ay, az, aw);
        *(float4*)&g_hp1[node * 64 + c4 * 4] = o;
        int head = c4 >> 2;
        int c = c4 * 4;
        asv[head] += ax * sAs[c] + ay * sAs[c + 1] + az * sAs[c + 2] + aw * sAs[c + 3];
        adv[head] += ax * sAd[c] + ay * sAd[c + 1] + az * sAd[c + 2] + aw * sAd[c + 3];
    }
#pragma unroll
    for (int h = 0; h < 4; h++) {
        g_as1[node * 4 + h] = asv[h];
        g_ad1[node * 4 + h] = adv[h];
        g_amax1[node * 4 + h] = lrelu(asv[h] + adv[h], 0.2f);  // self-loop seeds max
    }
}

// ---------------- kernel 2: edge max pass, gat1 ------------------------------
__global__ void k_emax1(const int* __restrict__ src, const int* __restrict__ dst, int e) {
    int t = blockIdx.x * blockDim.x + threadIdx.x;
    if (t >= e * 4) return;
    int ed = t >> 2, h = t & 3;
    int s = src[ed], d = dst[ed];
    float a = lrelu(g_as1[s * 4 + h] + g_ad1[d * 4 + h], 0.2f);
    atomicMaxF(&g_amax1[d * 4 + h], a);
}

// ---------------- kernel 3: self-loop init, gat1 -----------------------------
__global__ void k_self1(int n) {
    int t = blockIdx.x * blockDim.x + threadIdx.x;
    if (t >= n * 16) return;
    int node = t >> 4, c4 = t & 15;
    int h = c4 >> 2;
    float a = lrelu(g_as1[node * 4 + h] + g_ad1[node * 4 + h], 0.2f);
    float es = __expf(a - g_amax1[node * 4 + h]);
    if ((c4 & 3) == 0) g_asum1[node * 4 + h] = es;
    float4 v = *(const float4*)&g_hp1[node * 64 + c4 * 4];
    v.x *= es; v.y *= es; v.z *= es; v.w *= es;
    *(float4*)&g_out1[node * 64 + c4 * 4] = v;
}

// ---------------- kernel 4: edge message pass, gat1 --------------------------
__global__ void k_emsg1(const int* __restrict__ src, const int* __restrict__ dst, int e) {
    int t = blockIdx.x * blockDim.x + threadIdx.x;
    if (t >= e * 8) return;
    int ed = t >> 3, j = t & 7;
    int h = j >> 1;
    int s = src[ed], d = dst[ed];
    float a = lrelu(g_as1[s * 4 + h] + g_ad1[d * 4 + h], 0.2f);
    float w = __expf(a - g_amax1[d * 4 + h]);
    if ((j & 1) == 0) atomicAdd(&g_asum1[d * 4 + h], w);
    float4 v0 = *(const float4*)&g_hp1[s * 64 + j * 8];
    float4 v1 = *(const float4*)&g_hp1[s * 64 + j * 8 + 4];
    red4(&g_out1[d * 64 + j * 8],     w * v0.x, w * v0.y, w * v0.z, w * v0.w);
    red4(&g_out1[d * 64 + j * 8 + 4], w * v1.x, w * v1.y, w * v1.z, w * v1.w);
}

// ---------------- kernel 5: finish gat1 (elu) + gat2 projection --------------
__global__ void k_fin1_gat2(const float* __restrict__ g1b,
                            const float* __restrict__ g2W,
                            const float* __restrict__ g2as, const float* __restrict__ g2ad,
                            int n) {
    __shared__ __align__(16) float sW[64 * 64];
    __shared__ __align__(16) float sB[64], sAs[64], sAd[64];
    for (int i = threadIdx.x; i < 4096; i += blockDim.x) sW[i] = g2W[i];
    if (threadIdx.x < 64) {
        sB[threadIdx.x] = g1b[threadIdx.x];
        sAs[threadIdx.x] = g2as[threadIdx.x];
        sAd[threadIdx.x] = g2ad[threadIdx.x];
    }
    __syncthreads();
    int node = blockIdx.x * blockDim.x + threadIdx.x;
    if (node >= n) return;

    float inv[4];
#pragma unroll
    for (int h = 0; h < 4; h++) inv[h] = 1.0f / g_asum1[node * 4 + h];

    float h1[64];
#pragma unroll
    for (int c = 0; c < 64; c++) {
        float v = g_out1[node * 64 + c] * inv[c >> 4] + sB[c];
        h1[c] = v > 0.f ? v : expm1f(v);  // ELU
    }

    float as = 0.f, ad = 0.f;
    for (int c4 = 0; c4 < 16; c4++) {
        float ax = 0, ay = 0, az = 0, aw = 0;
#pragma unroll
        for (int k = 0; k < 64; k++) {
            float4 w = *(const float4*)&sW[k * 64 + c4 * 4];
            ax = fmaf(h1[k], w.x, ax);
            ay = fmaf(h1[k], w.y, ay);
            az = fmaf(h1[k], w.z, az);
            aw = fmaf(h1[k], w.w, aw);
        }
        *(float4*)&g_hp2[node * 64 + c4 * 4] = make_float4(ax, ay, az, aw);
        int c = c4 * 4;
        as += ax * sAs[c] + ay * sAs[c + 1] + az * sAs[c + 2] + aw * sAs[c + 3];
        ad += ax * sAd[c] + ay * sAd[c + 1] + az * sAd[c + 2] + aw * sAd[c + 3];
    }
    g_as2[node] = as;
    g_ad2[node] = ad;
    g_amax2[node] = lrelu(as + ad, 0.2f);
}

// ---------------- kernel 6: edge max pass, gat2 ------------------------------
__global__ void k_emax2(const int* __restrict__ src, const int* __restrict__ dst, int e) {
    int t = blockIdx.x * blockDim.x + threadIdx.x;
    if (t >= e) return;
    int s = src[t], d = dst[t];
    float a = lrelu(g_as2[s] + g_ad2[d], 0.2f);
    atomicMaxF(&g_amax2[d], a);
}

// ---------------- kernel 7: self-loop init, gat2 -----------------------------
__global__ void k_self2(int n) {
    int t = blockIdx.x * blockDim.x + threadIdx.x;
    if (t >= n * 16) return;
    int node = t >> 4, c4 = t & 15;
    float a = lrelu(g_as2[node] + g_ad2[node], 0.2f);
    float es = __expf(a - g_amax2[node]);
    if (c4 == 0) g_asum2[node] = es;
    float4 v = *(const float4*)&g_hp2[node * 64 + c4 * 4];
    v.x *= es; v.y *= es; v.z *= es; v.w *= es;
    *(float4*)&g_out2[node * 64 + c4 * 4] = v;
}

// ---------------- kernel 8: edge message pass, gat2 --------------------------
__global__ void k_emsg2(const int* __restrict__ src, const int* __restrict__ dst, int e) {
    int t = blockIdx.x * blockDim.x + threadIdx.x;
    if (t >= e * 8) return;
    int ed = t >> 3, j = t & 7;
    int s = src[ed], d = dst[ed];
    float a = lrelu(g_as2[s] + g_ad2[d], 0.2f);
    float w = __expf(a - g_amax2[d]);
    if (j == 0) atomicAdd(&g_asum2[d], w);
    float4 v0 = *(const float4*)&g_hp2[s * 64 + j * 8];
    float4 v1 = *(const float4*)&g_hp2[s * 64 + j * 8 + 4];
    red4(&g_out2[d * 64 + j * 8],     w * v0.x, w * v0.y, w * v0.z, w * v0.w);
    red4(&g_out2[d * 64 + j * 8 + 4], w * v1.x, w * v1.y, w * v1.z, w * v1.w);
}

// ---------------- kernel 9a: finish gat2 + edge-head node precompute ---------
// h2 = out2/asum2 + g2_b ; EA = h2 @ eoW1[0:64] + eo_b1 ; EB = h2 @ eoW1[64:128]
__global__ void k_fin2_eab(const float* __restrict__ g2b,
                           const float* __restrict__ eoW1, const float* __restrict__ eob1,
                           int n) {
    __shared__ __align__(16) float sWa[64 * 64];
    __shared__ __align__(16) float sWb[64 * 64];
    __shared__ __align__(16) float sB[64], sB1[64];
    for (int i = threadIdx.x; i < 4096; i += blockDim.x) {
        sWa[i] = eoW1[i];
        sWb[i] = eoW1[4096 + i];
    }
    if (threadIdx.x < 64) {
        sB[threadIdx.x] = g2b[threadIdx.x];
        sB1[threadIdx.x] = eob1[threadIdx.x];
    }
    __syncthreads();
    int node = blockIdx.x * blockDim.x + threadIdx.x;
    if (node >= n) return;

    float inv = 1.0f / g_asum2[node];
    float h2[64];
#pragma unroll
    for (int c = 0; c < 64; c++) {
        float v = g_out2[node * 64 + c] * inv + sB[c];
        h2[c] = v;
        g_h2[node * 64 + c] = v;
    }

    for (int c4 = 0; c4 < 16; c4++) {
        float ax = 0, ay = 0, az = 0, aw = 0;
        float bx = 0, by = 0, bz = 0, bw = 0;
#pragma unroll
        for (int k = 0; k < 64; k++) {
            float hv = h2[k];
            float4 wa = *(const float4*)&sWa[k * 64 + c4 * 4];
            float4 wb = *(const float4*)&sWb[k * 64 + c4 * 4];
            ax = fmaf(hv, wa.x, ax); ay = fmaf(hv, wa.y, ay);
            az = fmaf(hv, wa.z, az); aw = fmaf(hv, wa.w, aw);
            bx = fmaf(hv, wb.x, bx); by = fmaf(hv, wb.y, by);
            bz = fmaf(hv, wb.z, bz); bw = fmaf(hv, wb.w, bw);
        }
        int c = c4 * 4;
        *(float4*)&g_EA[node * 64 + c] =
            make_float4(ax + sB1[c], ay + sB1[c + 1], az + sB1[c + 2], aw + sB1[c + 3]);
        *(float4*)&g_EB[node * 64 + c] = make_float4(bx, by, bz, bw);
    }
}

// ---------------- kernel 9b: node prediction head ----------------------------
__global__ void k_nodehead(const float* __restrict__ noW1, const float* __restrict__ nob1,
                           const float* __restrict__ noW2, const float* __restrict__ nob2,
                           float* __restrict__ out, int n, int e) {
    __shared__ __align__(16) float sW[64 * 64];
    __shared__ __align__(16) float sB1[64], sW2[128];
    for (int i = threadIdx.x; i < 4096; i += blockDim.x) sW[i] = noW1[i];
    if (threadIdx.x < 64) sB1[threadIdx.x] = nob1[threadIdx.x];
    if (threadIdx.x < 128) sW2[threadIdx.x] = noW2[threadIdx.x];
    __syncthreads();
    int node = blockIdx.x * blockDim.x + threadIdx.x;
    if (node >= n) return;

    float h2[64];
#pragma unroll
    for (int c = 0; c < 64; c++) h2[c] = g_h2[node * 64 + c];

    float p0 = 0.f, p1 = 0.f;
    for (int c = 0; c < 64; c++) {
        float acc = sB1[c];
#pragma unroll
        for (int k = 0; k < 64; k++) acc = fmaf(h2[k], sW[k * 64 + c], acc);
        float t = lrelu(acc, 0.01f);
        p0 = fmaf(t, sW2[c * 2], p0);
        p1 = fmaf(t, sW2[c * 2 + 1], p1);
    }
    out[e + node * 2]     = tanhf(p0 + nob2[0]);
    out[e + node * 2 + 1] = tanhf(p1 + nob2[1]);
}

// ---------------- kernel 10: edge prediction head ----------------------------
__global__ void k_edgehead(const int* __restrict__ src, const int* __restrict__ dst,
                           const float* __restrict__ eattr,
                           const float* __restrict__ eoW1,
                           const float* __restrict__ eoW2, const float* __restrict__ eob2,
                           float* __restrict__ out, int e) {
    __shared__ __align__(16) float sW128[64], sW129[64], sW2[64];
    __shared__ float sB2;
    if (threadIdx.x < 64) {
        sW128[threadIdx.x] = eoW1[128 * 64 + threadIdx.x];
        sW129[threadIdx.x] = eoW1[129 * 64 + threadIdx.x];
        sW2[threadIdx.x] = eoW2[threadIdx.x];
    }
    if (threadIdx.x == 0) sB2 = eob2[0];
    __syncthreads();
    int t = blockIdx.x * blockDim.x + threadIdx.x;
    if (t >= e * 8) return;
    int ed = t >> 3, j = t & 7;
    int s = src[ed], d = dst[ed];
    float ea0 = eattr[ed * 2], ea1 = eattr[ed * 2 + 1];

    float partial = 0.f;
    int c0 = j * 8;
#pragma unroll
    for (int half = 0; half < 2; half++) {
        int c = c0 + half * 4;
        float4 va = *(const float4*)&g_EA[s * 64 + c];
        float4 vb = *(const float4*)&g_EB[d * 64 + c];
        float pre;
        pre = va.x + vb.x + ea0 * sW128[c]     + ea1 * sW129[c];
        partial = fmaf(lrelu(pre, 0.01f), sW2[c], partial);
        pre = va.y + vb.y + ea0 * sW128[c + 1] + ea1 * sW129[c + 1];
        partial = fmaf(lrelu(pre, 0.01f), sW2[c + 1], partial);
        pre = va.z + vb.z + ea0 * sW128[c + 2] + ea1 * sW129[c + 2];
        partial = fmaf(lrelu(pre, 0.01f), sW2[c + 2], partial);
        pre = va.w + vb.w + ea0 * sW128[c + 3] + ea1 * sW129[c + 3];
        partial = fmaf(lrelu(pre, 0.01f), sW2[c + 3], partial);
    }
    // reduce over 8 lanes of the edge group
    partial += __shfl_xor_sync(0xffffffffu, partial, 4);
    partial += __shfl_xor_sync(0xffffffffu, partial, 2);
    partial += __shfl_xor_sync(0xffffffffu, partial, 1);
    if (j == 0) out[ed] = tanhf(partial + sB2);
}

// ---------------- launch ------------------------------------------------------
extern "C" void kernel_launch(void* const* d_in, const int* in_sizes, int n_in,
                              void* d_out, int out_size) {
    const float* x      = (const float*)d_in[0];
    const int*   eidx   = (const int*)d_in[1];
    const float* eattr  = (const float*)d_in[2];
    const float* encW   = (const float*)d_in[3];
    const float* encb   = (const float*)d_in[4];
    const float* g1W    = (const float*)d_in[5];
    const float* g1as   = (const float*)d_in[6];
    const float* g1ad   = (const float*)d_in[7];
    const float* g1b    = (const float*)d_in[8];
    const float* g2W    = (const float*)d_in[9];
    const float* g2as   = (const float*)d_in[10];
    const float* g2ad   = (const float*)d_in[11];
    const float* g2b    = (const float*)d_in[12];
    const float* noW1   = (const float*)d_in[13];
    const float* nob1   = (const float*)d_in[14];
    const float* noW2   = (const float*)d_in[15];
    const float* nob2   = (const float*)d_in[16];
    const float* eoW1   = (const float*)d_in[17];
    const float* eob1   = (const float*)d_in[18];
    const float* eoW2   = (const float*)d_in[19];
    const float* eob2   = (const float*)d_in[20];
    float* out = (float*)d_out;

    int n = in_sizes[0] / 2;
    int e = in_sizes[1] / 2;
    const int* src = eidx;
    const int* dst = eidx + e;

    const int B = 256;
    int gn   = (n + B - 1) / B;
    int gn16 = (n * 16 + B - 1) / B;
    int ge1  = (e + B - 1) / B;
    int ge4  = (e * 4 + B - 1) / B;
    int ge8  = (e * 8 + B - 1) / B;

    k_enc_gat1<<<gn, B>>>(x, encW, encb, g1W, g1as, g1ad, n);
    k_emax1<<<ge4, B>>>(src, dst, e);
    k_self1<<<gn16, B>>>(n);
    k_emsg1<<<ge8, B>>>(src, dst, e);
    k_fin1_gat2<<<gn, B>>>(g1b, g2W, g2as, g2ad, n);
    k_emax2<<<ge1, B>>>(src, dst, e);
    k_self2<<<gn16, B>>>(n);
    k_emsg2<<<ge8, B>>>(src, dst, e);
    k_fin2_eab<<<gn, B>>>(g2b, eoW1, eob1, n);
    k_nodehead<<<gn, B>>>(noW1, nob1, noW2, nob2, out, n, e);
    k_edgehead<<<ge8, B>>>(src, dst, eattr, eoW1, eoW2, eob2, out, e);
}

// round 2
// speedup vs baseline: 1.2116x; 1.2116x over previous
#include <cuda_runtime.h>

#define NN 100000
#define EE 1600000

// ---------------- scratch (static device globals; no allocation) ------------
__device__ float g_hp1[NN * 64];
__device__ float g_out1[NN * 64];
__device__ float g_as1[NN * 4];
__device__ float g_ad1[NN * 4];
__device__ float g_asum1[NN * 4];
__device__ float g_hp2[NN * 64];
__device__ float g_out2[NN * 64];
__device__ float g_as2[NN];
__device__ float g_ad2[NN];
__device__ float g_asum2[NN];
__device__ float g_EA[NN * 64];
__device__ float g_EB[NN * 64];

// ---------------- helpers ---------------------------------------------------
__device__ __forceinline__ float lrelu(float x, float s) { return x > 0.f ? x : s * x; }

// vector reduction-add (sm_90+): 1 instruction scatters 16B
__device__ __forceinline__ void red4(float* a, float x, float y, float z, float w) {
    asm volatile("red.global.add.v4.f32 [%0], {%1,%2,%3,%4};"
                 :: "l"(a), "f"(x), "f"(y), "f"(z), "f"(w) : "memory");
}
__device__ __forceinline__ void red1(float* a, float x) {
    asm volatile("red.global.add.f32 [%0], %1;" :: "l"(a), "f"(x) : "memory");
}

// ---------------- kernel 1: encoder + gat1 projection + self-loop seed -------
__global__ void k_enc_gat1(const float* __restrict__ x,
                           const float* __restrict__ encW, const float* __restrict__ encb,
                           const float* __restrict__ g1W,
                           const float* __restrict__ g1as, const float* __restrict__ g1ad,
                           int n) {
    __shared__ __align__(16) float sW[64 * 64];
    __shared__ __align__(16) float sEnc[128];
    __shared__ __align__(16) float sEb[64], sAs[64], sAd[64];
    for (int i = threadIdx.x; i < 4096; i += blockDim.x) sW[i] = g1W[i];
    if (threadIdx.x < 128) sEnc[threadIdx.x] = encW[threadIdx.x];
    if (threadIdx.x < 64) {
        sEb[threadIdx.x] = encb[threadIdx.x];
        sAs[threadIdx.x] = g1as[threadIdx.x];
        sAd[threadIdx.x] = g1ad[threadIdx.x];
    }
    __syncthreads();
    int node = blockIdx.x * blockDim.x + threadIdx.x;
    if (node >= n) return;

    float x0 = x[node * 2], x1 = x[node * 2 + 1];
    float h0[64];
#pragma unroll
    for (int k = 0; k < 64; k++)
        h0[k] = fmaf(x0, sEnc[k], fmaf(x1, sEnc[64 + k], sEb[k]));

    float hp[64];
    float asv[4] = {0, 0, 0, 0}, adv[4] = {0, 0, 0, 0};
    for (int c4 = 0; c4 < 16; c4++) {
        float ax = 0, ay = 0, az = 0, aw = 0;
#pragma unroll
        for (int k = 0; k < 64; k++) {
            float4 w = *(const float4*)&sW[k * 64 + c4 * 4];
            ax = fmaf(h0[k], w.x, ax);
            ay = fmaf(h0[k], w.y, ay);
            az = fmaf(h0[k], w.z, az);
            aw = fmaf(h0[k], w.w, aw);
        }
        int c = c4 * 4;
        hp[c] = ax; hp[c + 1] = ay; hp[c + 2] = az; hp[c + 3] = aw;
        *(float4*)&g_hp1[node * 64 + c] = make_float4(ax, ay, az, aw);
        int head = c4 >> 2;
        asv[head] += ax * sAs[c] + ay * sAs[c + 1] + az * sAs[c + 2] + aw * sAs[c + 3];
        adv[head] += ax * sAd[c] + ay * sAd[c + 1] + az * sAd[c + 2] + aw * sAd[c + 3];
    }
    float es[4];
#pragma unroll
    for (int h = 0; h < 4; h++) {
        g_as1[node * 4 + h] = asv[h];
        g_ad1[node * 4 + h] = adv[h];
        es[h] = __expf(lrelu(asv[h] + adv[h], 0.2f));  // self-loop weight (no max shift)
    }
    *(float4*)&g_asum1[node * 4] = make_float4(es[0], es[1], es[2], es[3]);
#pragma unroll
    for (int c4 = 0; c4 < 16; c4++) {
        int c = c4 * 4;
        float e0 = es[c4 >> 2];
        *(float4*)&g_out1[node * 64 + c] =
            make_float4(hp[c] * e0, hp[c + 1] * e0, hp[c + 2] * e0, hp[c + 3] * e0);
    }
}

// ---------------- kernel 2: edge message pass, gat1 (4 lanes/edge, lane=head)
__global__ void k_emsg1(const int* __restrict__ src, const int* __restrict__ dst, int e) {
    int t = blockIdx.x * blockDim.x + threadIdx.x;
    if (t >= e * 4) return;
    int ed = t >> 2, j = t & 3;               // j = head index
    int s = src[ed], d = dst[ed];
    float a = lrelu(g_as1[s * 4 + j] + g_ad1[d * 4 + j], 0.2f);
    float w = __expf(a);
    // one red4 per edge for the 4 head sums (gather via width-4 shuffles)
    float w1 = __shfl_sync(0xffffffffu, w, 1, 4);
    float w2 = __shfl_sync(0xffffffffu, w, 2, 4);
    float w3 = __shfl_sync(0xffffffffu, w, 3, 4);
    if (j == 0) red4(&g_asum1[d * 4], w, w1, w2, w3);
    // this head's 16 channels: 4 x LDG.128 + 4 x RED.128
    const float4* hp = (const float4*)&g_hp1[s * 64 + j * 16];
    float* o = &g_out1[d * 64 + j * 16];
    float4 v0 = __ldg(hp), v1 = __ldg(hp + 1), v2 = __ldg(hp + 2), v3 = __ldg(hp + 3);
    red4(o,      w * v0.x, w * v0.y, w * v0.z, w * v0.w);
    red4(o + 4,  w * v1.x, w * v1.y, w * v1.z, w * v1.w);
    red4(o + 8,  w * v2.x, w * v2.y, w * v2.z, w * v2.w);
    red4(o + 12, w * v3.x, w * v3.y, w * v3.z, w * v3.w);
}

// ---------------- kernel 3: finish gat1 (elu) + gat2 projection + seed -------
__global__ void k_fin1_gat2(const float* __restrict__ g1b,
                            const float* __restrict__ g2W,
                            const float* __restrict__ g2as, const float* __restrict__ g2ad,
                            int n) {
    __shared__ __align__(16) float sW[64 * 64];
    __shared__ __align__(16) float sB[64], sAs[64], sAd[64];
    for (int i = threadIdx.x; i < 4096; i += blockDim.x) sW[i] = g2W[i];
    if (threadIdx.x < 64) {
        sB[threadIdx.x] = g1b[threadIdx.x];
        sAs[threadIdx.x] = g2as[threadIdx.x];
        sAd[threadIdx.x] = g2ad[threadIdx.x];
    }
    __syncthreads();
    int node = blockIdx.x * blockDim.x + threadIdx.x;
    if (node >= n) return;

    float inv[4];
#pragma unroll
    for (int h = 0; h < 4; h++) inv[h] = 1.0f / g_asum1[node * 4 + h];

    float h1[64];
#pragma unroll
    for (int c = 0; c < 64; c++) {
        float v = g_out1[node * 64 + c] * inv[c >> 4] + sB[c];
        h1[c] = v > 0.f ? v : expm1f(v);  // ELU
    }

    float hp[64];
    float as = 0.f, ad = 0.f;
    for (int c4 = 0; c4 < 16; c4++) {
        float ax = 0, ay = 0, az = 0, aw = 0;
#pragma unroll
        for (int k = 0; k < 64; k++) {
            float4 w = *(const float4*)&sW[k * 64 + c4 * 4];
            ax = fmaf(h1[k], w.x, ax);
            ay = fmaf(h1[k], w.y, ay);
            az = fmaf(h1[k], w.z, az);
            aw = fmaf(h1[k], w.w, aw);
        }
        int c = c4 * 4;
        hp[c] = ax; hp[c + 1] = ay; hp[c + 2] = az; hp[c + 3] = aw;
        *(float4*)&g_hp2[node * 64 + c] = make_float4(ax, ay, az, aw);
        as += ax * sAs[c] + ay * sAs[c + 1] + az * sAs[c + 2] + aw * sAs[c + 3];
        ad += ax * sAd[c] + ay * sAd[c + 1] + az * sAd[c + 2] + aw * sAd[c + 3];
    }
    g_as2[node] = as;
    g_ad2[node] = ad;
    float es = __expf(lrelu(as + ad, 0.2f));
    g_asum2[node] = es;
#pragma unroll
    for (int c4 = 0; c4 < 16; c4++) {
        int c = c4 * 4;
        *(float4*)&g_out2[node * 64 + c] =
            make_float4(hp[c] * es, hp[c + 1] * es, hp[c + 2] * es, hp[c + 3] * es);
    }
}

// ---------------- kernel 4: edge message pass, gat2 (4 lanes/edge) -----------
__global__ void k_emsg2(const int* __restrict__ src, const int* __restrict__ dst, int e) {
    int t = blockIdx.x * blockDim.x + threadIdx.x;
    if (t >= e * 4) return;
    int ed = t >> 2, j = t & 3;
    int s = src[ed], d = dst[ed];
    float w = __expf(lrelu(g_as2[s] + g_ad2[d], 0.2f));
    if (j == 0) red1(&g_asum2[d], w);
    const float4* hp = (const float4*)&g_hp2[s * 64 + j * 16];
    float* o = &g_out2[d * 64 + j * 16];
    float4 v0 = __ldg(hp), v1 = __ldg(hp + 1), v2 = __ldg(hp + 2), v3 = __ldg(hp + 3);
    red4(o,      w * v0.x, w * v0.y, w * v0.z, w * v0.w);
    red4(o + 4,  w * v1.x, w * v1.y, w * v1.z, w * v1.w);
    red4(o + 8,  w * v2.x, w * v2.y, w * v2.z, w * v2.w);
    red4(o + 12, w * v3.x, w * v3.y, w * v3.z, w * v3.w);
}

// ---------------- kernel 5: finish gat2 + edge-head precompute + node head ---
__global__ void k_fin2_heads(const float* __restrict__ g2b,
                             const float* __restrict__ eoW1, const float* __restrict__ eob1,
                             const float* __restrict__ noW1, const float* __restrict__ nob1,
                             const float* __restrict__ noW2, const float* __restrict__ nob2,
                             float* __restrict__ out, int n, int e) {
    __shared__ __align__(16) float sWa[64 * 64];
    __shared__ __align__(16) float sWb[64 * 64];
    __shared__ __align__(16) float sWn[64 * 64];
    __shared__ __align__(16) float sB[64], sB1[64], sBn[64], sW2[128];
    for (int i = threadIdx.x; i < 4096; i += blockDim.x) {
        sWa[i] = eoW1[i];
        sWb[i] = eoW1[4096 + i];
        sWn[i] = noW1[i];
    }
    if (threadIdx.x < 64) {
        sB[threadIdx.x]  = g2b[threadIdx.x];
        sB1[threadIdx.x] = eob1[threadIdx.x];
        sBn[threadIdx.x] = nob1[threadIdx.x];
    }
    if (threadIdx.x < 128) sW2[threadIdx.x] = noW2[threadIdx.x];
    __syncthreads();
    int node = blockIdx.x * blockDim.x + threadIdx.x;
    if (node >= n) return;

    float inv = 1.0f / g_asum2[node];
    float h2[64];
#pragma unroll
    for (int c = 0; c < 64; c++)
        h2[c] = g_out2[node * 64 + c] * inv + sB[c];

    float p0 = 0.f, p1 = 0.f;
    for (int c4 = 0; c4 < 16; c4++) {
        int c = c4 * 4;
        float ax = 0, ay = 0, az = 0, aw = 0;
        float bx = 0, by = 0, bz = 0, bw = 0;
        float nx = sBn[c], ny = sBn[c + 1], nz = sBn[c + 2], nw = sBn[c + 3];
#pragma unroll
        for (int k = 0; k < 64; k++) {
            float hv = h2[k];
            float4 wa = *(const float4*)&sWa[k * 64 + c];
            float4 wb = *(const float4*)&sWb[k * 64 + c];
            float4 wn = *(const float4*)&sWn[k * 64 + c];
            ax = fmaf(hv, wa.x, ax); ay = fmaf(hv, wa.y, ay);
            az = fmaf(hv, wa.z, az); aw = fmaf(hv, wa.w, aw);
            bx = fmaf(hv, wb.x, bx); by = fmaf(hv, wb.y, by);
            bz = fmaf(hv, wb.z, bz); bw = fmaf(hv, wb.w, bw);
            nx = fmaf(hv, wn.x, nx); ny = fmaf(hv, wn.y, ny);
            nz = fmaf(hv, wn.z, nz); nw = fmaf(hv, wn.w, nw);
        }
        *(float4*)&g_EA[node * 64 + c] =
            make_float4(ax + sB1[c], ay + sB1[c + 1], az + sB1[c + 2], aw + sB1[c + 3]);
        *(float4*)&g_EB[node * 64 + c] = make_float4(bx, by, bz, bw);
        float t0 = lrelu(nx, 0.01f), t1 = lrelu(ny, 0.01f);
        float t2 = lrelu(nz, 0.01f), t3 = lrelu(nw, 0.01f);
        p0 = fmaf(t0, sW2[c * 2],     fmaf(t1, sW2[c * 2 + 2],
             fmaf(t2, sW2[c * 2 + 4], fmaf(t3, sW2[c * 2 + 6], p0))));
        p1 = fmaf(t0, sW2[c * 2 + 1], fmaf(t1, sW2[c * 2 + 3],
             fmaf(t2, sW2[c * 2 + 5], fmaf(t3, sW2[c * 2 + 7], p1))));
    }
    out[e + node * 2]     = tanhf(p0 + nob2[0]);
    out[e + node * 2 + 1] = tanhf(p1 + nob2[1]);
}

// ---------------- kernel 6: edge prediction head (4 lanes/edge) --------------
__global__ void k_edgehead(const int* __restrict__ src, const int* __restrict__ dst,
                           const float* __restrict__ eattr,
                           const float* __restrict__ eoW1,
                           const float* __restrict__ eoW2, const float* __restrict__ eob2,
                           float* __restrict__ out, int e) {
    __shared__ __align__(16) float sW128[64], sW129[64], sW2[64];
    __shared__ float sB2;
    if (threadIdx.x < 64) {
        sW128[threadIdx.x] = eoW1[128 * 64 + threadIdx.x];
        sW129[threadIdx.x] = eoW1[129 * 64 + threadIdx.x];
        sW2[threadIdx.x] = eoW2[threadIdx.x];
    }
    if (threadIdx.x == 0) sB2 = eob2[0];
    __syncthreads();
    int t = blockIdx.x * blockDim.x + threadIdx.x;
    if (t >= e * 4) return;
    int ed = t >> 2, j = t & 3;
    int s = src[ed], d = dst[ed];
    float ea0 = eattr[ed * 2], ea1 = eattr[ed * 2 + 1];

    float partial = 0.f;
    int c0 = j * 16;
    const float4* pa = (const float4*)&g_EA[s * 64 + c0];
    const float4* pb = (const float4*)&g_EB[d * 64 + c0];
#pragma unroll
    for (int q = 0; q < 4; q++) {
        int c = c0 + q * 4;
        float4 va = __ldg(pa + q);
        float4 vb = __ldg(pb + q);
        float pre;
        pre = va.x + vb.x + ea0 * sW128[c]     + ea1 * sW129[c];
        partial = fmaf(lrelu(pre, 0.01f), sW2[c], partial);
        pre = va.y + vb.y + ea0 * sW128[c + 1] + ea1 * sW129[c + 1];
        partial = fmaf(lrelu(pre, 0.01f), sW2[c + 1], partial);
        pre = va.z + vb.z + ea0 * sW128[c + 2] + ea1 * sW129[c + 2];
        partial = fmaf(lrelu(pre, 0.01f), sW2[c + 2], partial);
        pre = va.w + vb.w + ea0 * sW128[c + 3] + ea1 * sW129[c + 3];
        partial = fmaf(lrelu(pre, 0.01f), sW2[c + 3], partial);
    }
    partial += __shfl_xor_sync(0xffffffffu, partial, 2);
    partial += __shfl_xor_sync(0xffffffffu, partial, 1);
    if (j == 0) out[ed] = tanhf(partial + sB2);
}

// ---------------- launch ------------------------------------------------------
extern "C" void kernel_launch(void* const* d_in, const int* in_sizes, int n_in,
                              void* d_out, int out_size) {
    const float* x      = (const float*)d_in[0];
    const int*   eidx   = (const int*)d_in[1];
    const float* eattr  = (const float*)d_in[2];
    const float* encW   = (const float*)d_in[3];
    const float* encb   = (const float*)d_in[4];
    const float* g1W    = (const float*)d_in[5];
    const float* g1as   = (const float*)d_in[6];
    const float* g1ad   = (const float*)d_in[7];
    const float* g1b    = (const float*)d_in[8];
    const float* g2W    = (const float*)d_in[9];
    const float* g2as   = (const float*)d_in[10];
    const float* g2ad   = (const float*)d_in[11];
    const float* g2b    = (const float*)d_in[12];
    const float* noW1   = (const float*)d_in[13];
    const float* nob1   = (const float*)d_in[14];
    const float* noW2   = (const float*)d_in[15];
    const float* nob2   = (const float*)d_in[16];
    const float* eoW1   = (const float*)d_in[17];
    const float* eob1   = (const float*)d_in[18];
    const float* eoW2   = (const float*)d_in[19];
    const float* eob2   = (const float*)d_in[20];
    float* out = (float*)d_out;

    int n = in_sizes[0] / 2;
    int e = in_sizes[1] / 2;
    const int* src = eidx;
    const int* dst = eidx + e;

    const int B = 256;
    int gn  = (n + B - 1) / B;
    int ge4 = (e * 4 + B - 1) / B;

    k_enc_gat1<<<gn, B>>>(x, encW, encb, g1W, g1as, g1ad, n);
    k_emsg1<<<ge4, B>>>(src, dst, e);
    k_fin1_gat2<<<gn, B>>>(g1b, g2W, g2as, g2ad, n);
    k_emsg2<<<ge4, B>>>(src, dst, e);
    k_fin2_heads<<<gn, B>>>(g2b, eoW1, eob1, noW1, nob1, noW2, nob2, out, n, e);
    k_edgehead<<<ge4, B>>>(src, dst, eattr, eoW1, eoW2, eob2, out, e);
}

// round 3
// speedup vs baseline: 1.3448x; 1.1099x over previous
#include <cuda_runtime.h>

#define NN 100000
#define EE 1600000
#define NCHUNK 128
#define CH 782   // ceil(100000/128)

// ---------------- scratch (static device globals) ----------------------------
__device__ float g_hp1[NN * 64];
__device__ float g_out1[NN * 64];
__device__ float g_as1[NN * 4];
__device__ float g_ad1[NN * 4];
__device__ float g_asum1[NN * 4];
__device__ float g_hp2[NN * 64];
__device__ float g_out2[NN * 64];
__device__ float g_as2[NN];
__device__ float g_ad2[NN];
__device__ float g_asum2[NN];
__device__ float g_EA[NN * 64];
__device__ float g_EB[NN * 64];
// CSR build
__device__ int  g_cnt[NN];
__device__ int  g_offs[NN + 1];
__device__ int  g_cur[NN];
__device__ int2 g_csr[EE];           // .x = src node, .y = edge id
__device__ int  g_bsum[NCHUNK];
__device__ int  g_boff[NCHUNK];

__device__ __forceinline__ float lrelu(float x, float s) { return x > 0.f ? x : s * x; }

// ==================== CSR build =============================================
__global__ void k_zero(int n) {
    int t = blockIdx.x * blockDim.x + threadIdx.x;
    if (t < n) g_cnt[t] = 0;
}
__global__ void k_hist(const int* __restrict__ dst, int e) {
    int t = blockIdx.x * blockDim.x + threadIdx.x;
    if (t < e) atomicAdd(&g_cnt[dst[t]], 1);
}
__global__ void k_chunksum(int n) {
    __shared__ int red[256];
    int b = blockIdx.x, t = threadIdx.x;
    int base = b * CH;
    int s = 0;
    for (int i = t; i < CH; i += 256)
        if (base + i < n) s += g_cnt[base + i];
    red[t] = s; __syncthreads();
    for (int o = 128; o > 0; o >>= 1) {
        if (t < o) red[t] += red[t + o];
        __syncthreads();
    }
    if (t == 0) g_bsum[b] = red[0];
}
__global__ void k_scanchunk() {
    if (threadIdx.x == 0) {
        int acc = 0;
        for (int i = 0; i < NCHUNK; i++) { g_boff[i] = acc; acc += g_bsum[i]; }
    }
}
__global__ void k_scanwrite(int n) {
    __shared__ int sd[1024];
    int b = blockIdx.x, t = threadIdx.x;
    int base = b * CH;
    int v = (t < CH && base + t < n) ? g_cnt[base + t] : 0;
    sd[t] = v; __syncthreads();
    for (int o = 1; o < 1024; o <<= 1) {
        int x = (t >= o) ? sd[t - o] : 0;
        __syncthreads();
        sd[t] += x;
        __syncthreads();
    }
    int excl = sd[t] - v + g_boff[b];
    if (t < CH && base + t < n) { g_offs[base + t] = excl; g_cur[base + t] = excl; }
    if (base + t == n - 1) g_offs[n] = excl + v;
}
__global__ void k_scatter(const int* __restrict__ src, const int* __restrict__ dst, int e) {
    int t = blockIdx.x * blockDim.x + threadIdx.x;
    if (t >= e) return;
    int d = dst[t];
    int pos = atomicAdd(&g_cur[d], 1);
    g_csr[pos] = make_int2(src[t], t);
}

// ==================== kernel: encoder + gat1 projection + self seed ==========
__global__ void k_enc_gat1(const float* __restrict__ x,
                           const float* __restrict__ encW, const float* __restrict__ encb,
                           const float* __restrict__ g1W,
                           const float* __restrict__ g1as, const float* __restrict__ g1ad,
                           int n) {
    __shared__ __align__(16) float sW[64 * 64];
    __shared__ __align__(16) float sEnc[128];
    __shared__ __align__(16) float sEb[64], sAs[64], sAd[64];
    for (int i = threadIdx.x; i < 4096; i += blockDim.x) sW[i] = g1W[i];
    if (threadIdx.x < 128) sEnc[threadIdx.x] = encW[threadIdx.x];
    if (threadIdx.x < 64) {
        sEb[threadIdx.x] = encb[threadIdx.x];
        sAs[threadIdx.x] = g1as[threadIdx.x];
        sAd[threadIdx.x] = g1ad[threadIdx.x];
    }
    __syncthreads();
    int node = blockIdx.x * blockDim.x + threadIdx.x;
    if (node >= n) return;

    float x0 = x[node * 2], x1 = x[node * 2 + 1];
    float h0[64];
#pragma unroll
    for (int k = 0; k < 64; k++)
        h0[k] = fmaf(x0, sEnc[k], fmaf(x1, sEnc[64 + k], sEb[k]));

    float hp[64];
    float asv[4] = {0, 0, 0, 0}, adv[4] = {0, 0, 0, 0};
    for (int c4 = 0; c4 < 16; c4++) {
        float ax = 0, ay = 0, az = 0, aw = 0;
#pragma unroll
        for (int k = 0; k < 64; k++) {
            float4 w = *(const float4*)&sW[k * 64 + c4 * 4];
            ax = fmaf(h0[k], w.x, ax);
            ay = fmaf(h0[k], w.y, ay);
            az = fmaf(h0[k], w.z, az);
            aw = fmaf(h0[k], w.w, aw);
        }
        int c = c4 * 4;
        hp[c] = ax; hp[c + 1] = ay; hp[c + 2] = az; hp[c + 3] = aw;
        *(float4*)&g_hp1[node * 64 + c] = make_float4(ax, ay, az, aw);
        int head = c4 >> 2;
        asv[head] += ax * sAs[c] + ay * sAs[c + 1] + az * sAs[c + 2] + aw * sAs[c + 3];
        adv[head] += ax * sAd[c] + ay * sAd[c + 1] + az * sAd[c + 2] + aw * sAd[c + 3];
    }
    float es[4];
#pragma unroll
    for (int h = 0; h < 4; h++) {
        g_as1[node * 4 + h] = asv[h];
        g_ad1[node * 4 + h] = adv[h];
        es[h] = __expf(lrelu(asv[h] + adv[h], 0.2f));   // self-loop weight
    }
    *(float4*)&g_asum1[node * 4] = make_float4(es[0], es[1], es[2], es[3]);
#pragma unroll
    for (int c4 = 0; c4 < 16; c4++) {
        int c = c4 * 4;
        float e0 = es[c4 >> 2];
        *(float4*)&g_out1[node * 64 + c] =
            make_float4(hp[c] * e0, hp[c + 1] * e0, hp[c + 2] * e0, hp[c + 3] * e0);
    }
}

// ==================== kernel: gat1 gather pass (warp per dst node) ===========
__global__ void k_msg1(int n) {
    int warp = (blockIdx.x * blockDim.x + threadIdx.x) >> 5;
    if (warp >= n) return;
    int node = warp;
    int lane = threadIdx.x & 31;
    int beg = g_offs[node], end = g_offs[node + 1];

    float adh = g_ad1[node * 4 + (lane & 3)];           // ad for head (lane&3)
    float2 acc = *(const float2*)&g_out1[node * 64 + lane * 2];  // self seed
    float wsum = 0.f;                                   // per-lane, head (lane&3)

    for (int i = beg; i < end; i += 8) {
        int idx = i + (lane >> 2);                      // 8 edges, 4 lanes each
        int2 ce = (idx < end) ? g_csr[idx] : make_int2(node, 0);
        float a = g_as1[ce.x * 4 + (lane & 3)] + adh;
        float w8 = (idx < end) ? __expf(lrelu(a, 0.2f)) : 0.f;
        wsum += w8;
        int m = min(8, end - i);
        for (int k = 0; k < m; k++) {
            int   s  = __shfl_sync(0xffffffffu, ce.x, k * 4);
            float wl = __shfl_sync(0xffffffffu, w8, k * 4 + (lane >> 3)); // head=lane>>3
            float2 v = *(const float2*)&g_hp1[s * 64 + lane * 2];
            acc.x = fmaf(wl, v.x, acc.x);
            acc.y = fmaf(wl, v.y, acc.y);
        }
    }
    *(float2*)&g_out1[node * 64 + lane * 2] = acc;
    // reduce wsum across the 8 lane-groups (same head at lane&3)
    wsum += __shfl_xor_sync(0xffffffffu, wsum, 4);
    wsum += __shfl_xor_sync(0xffffffffu, wsum, 8);
    wsum += __shfl_xor_sync(0xffffffffu, wsum, 16);
    if (lane < 4) g_asum1[node * 4 + lane] += wsum;
}

// ==================== kernel: finish gat1 + gat2 projection + seed ===========
__global__ void k_fin1_gat2(const float* __restrict__ g1b,
                            const float* __restrict__ g2W,
                            const float* __restrict__ g2as, const float* __restrict__ g2ad,
                            int n) {
    __shared__ __align__(16) float sW[64 * 64];
    __shared__ __align__(16) float sB[64], sAs[64], sAd[64];
    for (int i = threadIdx.x; i < 4096; i += blockDim.x) sW[i] = g2W[i];
    if (threadIdx.x < 64) {
        sB[threadIdx.x] = g1b[threadIdx.x];
        sAs[threadIdx.x] = g2as[threadIdx.x];
        sAd[threadIdx.x] = g2ad[threadIdx.x];
    }
    __syncthreads();
    int node = blockIdx.x * blockDim.x + threadIdx.x;
    if (node >= n) return;

    float inv[4];
#pragma unroll
    for (int h = 0; h < 4; h++) inv[h] = 1.0f / g_asum1[node * 4 + h];

    float h1[64];
#pragma unroll
    for (int c = 0; c < 64; c++) {
        float v = g_out1[node * 64 + c] * inv[c >> 4] + sB[c];
        h1[c] = v > 0.f ? v : expm1f(v);
    }

    float hp[64];
    float as = 0.f, ad = 0.f;
    for (int c4 = 0; c4 < 16; c4++) {
        float ax = 0, ay = 0, az = 0, aw = 0;
#pragma unroll
        for (int k = 0; k < 64; k++) {
            float4 w = *(const float4*)&sW[k * 64 + c4 * 4];
            ax = fmaf(h1[k], w.x, ax);
            ay = fmaf(h1[k], w.y, ay);
            az = fmaf(h1[k], w.z, az);
            aw = fmaf(h1[k], w.w, aw);
        }
        int c = c4 * 4;
        hp[c] = ax; hp[c + 1] = ay; hp[c + 2] = az; hp[c + 3] = aw;
        *(float4*)&g_hp2[node * 64 + c] = make_float4(ax, ay, az, aw);
        as += ax * sAs[c] + ay * sAs[c + 1] + az * sAs[c + 2] + aw * sAs[c + 3];
        ad += ax * sAd[c] + ay * sAd[c + 1] + az * sAd[c + 2] + aw * sAd[c + 3];
    }
    g_as2[node] = as;
    g_ad2[node] = ad;
    float es = __expf(lrelu(as + ad, 0.2f));
    g_asum2[node] = es;
#pragma unroll
    for (int c4 = 0; c4 < 16; c4++) {
        int c = c4 * 4;
        *(float4*)&g_out2[node * 64 + c] =
            make_float4(hp[c] * es, hp[c + 1] * es, hp[c + 2] * es, hp[c + 3] * es);
    }
}

// ==================== kernel: gat2 gather pass (warp per dst node) ===========
__global__ void k_msg2(int n) {
    int warp = (blockIdx.x * blockDim.x + threadIdx.x) >> 5;
    if (warp >= n) return;
    int node = warp;
    int lane = threadIdx.x & 31;
    int beg = g_offs[node], end = g_offs[node + 1];

    float ad2 = g_ad2[node];
    float2 acc = *(const float2*)&g_out2[node * 64 + lane * 2];
    float wsum = 0.f;

    for (int i = beg; i < end; i += 32) {
        int idx = i + lane;
        int2 ce = (idx < end) ? g_csr[idx] : make_int2(node, 0);
        float a = g_as2[ce.x] + ad2;
        float w32 = (idx < end) ? __expf(lrelu(a, 0.2f)) : 0.f;
        wsum += w32;
        int m = min(32, end - i);
        for (int k = 0; k < m; k++) {
            int   s  = __shfl_sync(0xffffffffu, ce.x, k);
            float wl = __shfl_sync(0xffffffffu, w32, k);
            float2 v = *(const float2*)&g_hp2[s * 64 + lane * 2];
            acc.x = fmaf(wl, v.x, acc.x);
            acc.y = fmaf(wl, v.y, acc.y);
        }
    }
    *(float2*)&g_out2[node * 64 + lane * 2] = acc;
    wsum += __shfl_xor_sync(0xffffffffu, wsum, 16);
    wsum += __shfl_xor_sync(0xffffffffu, wsum, 8);
    wsum += __shfl_xor_sync(0xffffffffu, wsum, 4);
    wsum += __shfl_xor_sync(0xffffffffu, wsum, 2);
    wsum += __shfl_xor_sync(0xffffffffu, wsum, 1);
    if (lane == 0) g_asum2[node] += wsum;
}

// ==================== kernel: finish gat2 + edge precompute + node head ======
__global__ void k_fin2_heads(const float* __restrict__ g2b,
                             const float* __restrict__ eoW1, const float* __restrict__ eob1,
                             const float* __restrict__ noW1, const float* __restrict__ nob1,
                             const float* __restrict__ noW2, const float* __restrict__ nob2,
                             float* __restrict__ out, int n, int e) {
    __shared__ __align__(16) float sWa[64 * 64];
    __shared__ __align__(16) float sWb[64 * 64];
    __shared__ __align__(16) float sWn[64 * 64];
    __shared__ __align__(16) float sB[64], sB1[64], sBn[64], sW2[128];
    for (int i = threadIdx.x; i < 4096; i += blockDim.x) {
        sWa[i] = eoW1[i];
        sWb[i] = eoW1[4096 + i];
        sWn[i] = noW1[i];
    }
    if (threadIdx.x < 64) {
        sB[threadIdx.x]  = g2b[threadIdx.x];
        sB1[threadIdx.x] = eob1[threadIdx.x];
        sBn[threadIdx.x] = nob1[threadIdx.x];
    }
    if (threadIdx.x < 128) sW2[threadIdx.x] = noW2[threadIdx.x];
    __syncthreads();
    int node = blockIdx.x * blockDim.x + threadIdx.x;
    if (node >= n) return;

    float inv = 1.0f / g_asum2[node];
    float h2[64];
#pragma unroll
    for (int c = 0; c < 64; c++)
        h2[c] = g_out2[node * 64 + c] * inv + sB[c];

    float p0 = 0.f, p1 = 0.f;
    for (int c4 = 0; c4 < 16; c4++) {
        int c = c4 * 4;
        float ax = 0, ay = 0, az = 0, aw = 0;
        float bx = 0, by = 0, bz = 0, bw = 0;
        float nx = sBn[c], ny = sBn[c + 1], nz = sBn[c + 2], nw = sBn[c + 3];
#pragma unroll
        for (int k = 0; k < 64; k++) {
            float hv = h2[k];
            float4 wa = *(const float4*)&sWa[k * 64 + c];
            float4 wb = *(const float4*)&sWb[k * 64 + c];
            float4 wn = *(const float4*)&sWn[k * 64 + c];
            ax = fmaf(hv, wa.x, ax); ay = fmaf(hv, wa.y, ay);
            az = fmaf(hv, wa.z, az); aw = fmaf(hv, wa.w, aw);
            bx = fmaf(hv, wb.x, bx); by = fmaf(hv, wb.y, by);
            bz = fmaf(hv, wb.z, bz); bw = fmaf(hv, wb.w, bw);
            nx = fmaf(hv, wn.x, nx); ny = fmaf(hv, wn.y, ny);
            nz = fmaf(hv, wn.z, nz); nw = fmaf(hv, wn.w, nw);
        }
        *(float4*)&g_EA[node * 64 + c] =
            make_float4(ax + sB1[c], ay + sB1[c + 1], az + sB1[c + 2], aw + sB1[c + 3]);
        *(float4*)&g_EB[node * 64 + c] = make_float4(bx, by, bz, bw);
        float t0 = lrelu(nx, 0.01f), t1 = lrelu(ny, 0.01f);
        float t2 = lrelu(nz, 0.01f), t3 = lrelu(nw, 0.01f);
        p0 = fmaf(t0, sW2[c * 2],     fmaf(t1, sW2[c * 2 + 2],
             fmaf(t2, sW2[c * 2 + 4], fmaf(t3, sW2[c * 2 + 6], p0))));
        p1 = fmaf(t0, sW2[c * 2 + 1], fmaf(t1, sW2[c * 2 + 3],
             fmaf(t2, sW2[c * 2 + 5], fmaf(t3, sW2[c * 2 + 7], p1))));
    }
    out[e + node * 2]     = tanhf(p0 + nob2[0]);
    out[e + node * 2 + 1] = tanhf(p1 + nob2[1]);
}

// ==================== kernel: edge head (warp per dst node via CSR) ==========
__global__ void k_edgehead(const float* __restrict__ eattr,
                           const float* __restrict__ eoW1,
                           const float* __restrict__ eoW2, const float* __restrict__ eob2,
                           float* __restrict__ out, int n) {
    int warp = (blockIdx.x * blockDim.x + threadIdx.x) >> 5;
    if (warp >= n) return;
    int node = warp;
    int lane = threadIdx.x & 31;
    int beg = g_offs[node], end = g_offs[node + 1];
    if (beg == end) return;

    // per-lane constants for channels 2*lane, 2*lane+1
    float2 w128 = *(const float2*)&eoW1[128 * 64 + lane * 2];
    float2 w129 = *(const float2*)&eoW1[129 * 64 + lane * 2];
    float2 w2   = *(const float2*)&eoW2[lane * 2];
    float  b2   = eob2[0];
    float2 eb   = *(const float2*)&g_EB[node * 64 + lane * 2];  // dst part, loaded once

    for (int i = beg; i < end; i += 32) {
        int idx = i + lane;
        int2 ce = (idx < end) ? g_csr[idx] : make_int2(node, 0);
        float2 ea = *(const float2*)&eattr[ce.y * 2];
        int m = min(32, end - i);
        for (int k = 0; k < m; k++) {
            int   s   = __shfl_sync(0xffffffffu, ce.x, k);
            int   eid = __shfl_sync(0xffffffffu, ce.y, k);
            float ea0 = __shfl_sync(0xffffffffu, ea.x, k);
            float ea1 = __shfl_sync(0xffffffffu, ea.y, k);
            float2 va = *(const float2*)&g_EA[s * 64 + lane * 2];
            float pre0 = va.x + eb.x + ea0 * w128.x + ea1 * w129.x;
            float pre1 = va.y + eb.y + ea0 * w128.y + ea1 * w129.y;
            float p = lrelu(pre0, 0.01f) * w2.x + lrelu(pre1, 0.01f) * w2.y;
            p += __shfl_xor_sync(0xffffffffu, p, 16);
            p += __shfl_xor_sync(0xffffffffu, p, 8);
            p += __shfl_xor_sync(0xffffffffu, p, 4);
            p += __shfl_xor_sync(0xffffffffu, p, 2);
            p += __shfl_xor_sync(0xffffffffu, p, 1);
            if (lane == 0) out[eid] = tanhf(p + b2);
        }
    }
}

// ==================== launch ==================================================
extern "C" void kernel_launch(void* const* d_in, const int* in_sizes, int n_in,
                              void* d_out, int out_size) {
    const float* x      = (const float*)d_in[0];
    const int*   eidx   = (const int*)d_in[1];
    const float* eattr  = (const float*)d_in[2];
    const float* encW   = (const float*)d_in[3];
    const float* encb   = (const float*)d_in[4];
    const float* g1W    = (const float*)d_in[5];
    const float* g1as   = (const float*)d_in[6];
    const float* g1ad   = (const float*)d_in[7];
    const float* g1b    = (const float*)d_in[8];
    const float* g2W    = (const float*)d_in[9];
    const float* g2as   = (const float*)d_in[10];
    const float* g2ad   = (const float*)d_in[11];
    const float* g2b    = (const float*)d_in[12];
    const float* noW1   = (const float*)d_in[13];
    const float* nob1   = (const float*)d_in[14];
    const float* noW2   = (const float*)d_in[15];
    const float* nob2   = (const float*)d_in[16];
    const float* eoW1   = (const float*)d_in[17];
    const float* eob1   = (const float*)d_in[18];
    const float* eoW2   = (const float*)d_in[19];
    const float* eob2   = (const float*)d_in[20];
    float* out = (float*)d_out;

    int n = in_sizes[0] / 2;
    int e = in_sizes[1] / 2;
    const int* src = eidx;
    const int* dst = eidx + e;

    const int B = 256;
    int gn  = (n + B - 1) / B;
    int ge  = (e + B - 1) / B;
    int gw  = (n * 32 + B - 1) / B;   // warp per node

    // CSR build (dst-sorted)
    k_zero<<<gn, B>>>(n);
    k_hist<<<ge, B>>>(dst, e);
    k_chunksum<<<NCHUNK, 256>>>(n);
    k_scanchunk<<<1, 32>>>();
    k_scanwrite<<<NCHUNK, 1024>>>(n);
    k_scatter<<<ge, B>>>(src, dst, e);

    // pipeline
    k_enc_gat1<<<gn, B>>>(x, encW, encb, g1W, g1as, g1ad, n);
    k_msg1<<<gw, B>>>(n);
    k_fin1_gat2<<<gn, B>>>(g1b, g2W, g2as, g2ad, n);
    k_msg2<<<gw, B>>>(n);
    k_fin2_heads<<<gn, B>>>(g2b, eoW1, eob1, noW1, nob1, noW2, nob2, out, n, e);
    k_edgehead<<<gw, B>>>(eattr, eoW1, eoW2, eob2, out, n);
}

// round 5
// speedup vs baseline: 1.5093x; 1.1224x over previous
#include <cuda_runtime.h>
#include <cuda_fp16.h>

#define NN 100000
#define EE 1600000
#define NCHUNK 128
#define CH 782   // ceil(100000/128)

// ---------------- scratch (static device globals) ----------------------------
__device__ unsigned int g_hp1h[NN * 32];   // half2 bit patterns, 64ch/node
__device__ float g_out1[NN * 64];
__device__ float g_as1[NN * 4];
__device__ float g_ad1[NN * 4];
__device__ float g_asum1[NN * 4];
__device__ unsigned int g_hp2h[NN * 32];
__device__ float g_out2[NN * 64];
__device__ float g_as2[NN];
__device__ float g_ad2[NN];
__device__ float g_asum2[NN];
__device__ unsigned int g_EAh[NN * 32];    // fp16 EA
__device__ float g_EB[NN * 64];
// CSR build
__device__ int  g_cnt[NN];
__device__ int  g_offs[NN + 1];
__device__ int  g_cur[NN];
__device__ int2 g_csr[EE];                 // .x = src node, .y = edge id
__device__ int  g_bsum[NCHUNK];
__device__ int  g_boff[NCHUNK];

// ---------------- helpers ----------------------------------------------------
__device__ __forceinline__ float lrelu(float x, float s) { return x > 0.f ? x : s * x; }

typedef unsigned long long ull;
__device__ __forceinline__ ull pack2(float v) {
    ull r;
    unsigned int u = __float_as_uint(v);
    asm("mov.b64 %0, {%1, %1};" : "=l"(r) : "r"(u));
    return r;
}
__device__ __forceinline__ void fma2(ull& d, ull a, ull b) {
    asm("fma.rn.f32x2 %0, %1, %2, %3;" : "=l"(d) : "l"(a), "l"(b), "l"(d));
}
__device__ __forceinline__ float2 unpack2(ull v) {
    unsigned int lo, hi;
    asm("mov.b64 {%0, %1}, %2;" : "=r"(lo), "=r"(hi) : "l"(v));
    return make_float2(__uint_as_float(lo), __uint_as_float(hi));
}
__device__ __forceinline__ unsigned int h2bits(float a, float b) {
    __half2 h = __floats2half2_rn(a, b);
    return *(unsigned int*)&h;
}

// ==================== CSR build ==============================================
__global__ void k_zero(int n) {
    int t = blockIdx.x * blockDim.x + threadIdx.x;
    if (t < n) g_cnt[t] = 0;
}
__global__ void k_hist(const int* __restrict__ dst, int e) {
    int t = blockIdx.x * blockDim.x + threadIdx.x;
    if (t < e) atomicAdd(&g_cnt[dst[t]], 1);
}
__global__ void k_chunksum(int n) {
    __shared__ int red[256];
    int b = blockIdx.x, t = threadIdx.x;
    int base = b * CH;
    int s = 0;
    for (int i = t; i < CH; i += 256)
        if (base + i < n) s += g_cnt[base + i];
    red[t] = s; __syncthreads();
    for (int o = 128; o > 0; o >>= 1) {
        if (t < o) red[t] += red[t + o];
        __syncthreads();
    }
    if (t == 0) g_bsum[b] = red[0];
}
__global__ void k_scanchunk() {          // 1 block, NCHUNK threads, Hillis-Steele
    __shared__ int sd[NCHUNK];
    int t = threadIdx.x;
    int v = g_bsum[t];
    sd[t] = v; __syncthreads();
    for (int o = 1; o < NCHUNK; o <<= 1) {
        int x = (t >= o) ? sd[t - o] : 0;
        __syncthreads();
        sd[t] += x;
        __syncthreads();
    }
    g_boff[t] = sd[t] - v;               // exclusive
}
__global__ void k_scanwrite(int n) {
    __shared__ int sd[1024];
    int b = blockIdx.x, t = threadIdx.x;
    int base = b * CH;
    int v = (t < CH && base + t < n) ? g_cnt[base + t] : 0;
    sd[t] = v; __syncthreads();
    for (int o = 1; o < 1024; o <<= 1) {
        int x = (t >= o) ? sd[t - o] : 0;
        __syncthreads();
        sd[t] += x;
        __syncthreads();
    }
    int excl = sd[t] - v + g_boff[b];
    if (t < CH && base + t < n) { g_offs[base + t] = excl; g_cur[base + t] = excl; }
    if (base + t == n - 1) g_offs[n] = excl + v;
}
__global__ void k_scatter(const int* __restrict__ src, const int* __restrict__ dst, int e) {
    int t = blockIdx.x * blockDim.x + threadIdx.x;
    if (t >= e) return;
    int d = dst[t];
    int pos = atomicAdd(&g_cur[d], 1);
    g_csr[pos] = make_int2(src[t], t);
}

// ==================== kernel: encoder + gat1 projection (FFMA2) ==============
__global__ void k_enc_gat1(const float* __restrict__ x,
                           const float* __restrict__ encW, const float* __restrict__ encb,
                           const float* __restrict__ g1W,
                           const float* __restrict__ g1as, const float* __restrict__ g1ad,
                           int n) {
    __shared__ __align__(16) float sW[64 * 64];
    __shared__ __align__(16) float sEnc[128];
    __shared__ __align__(16) float sEb[64], sAs[64], sAd[64];
    for (int i = threadIdx.x; i < 4096; i += blockDim.x) sW[i] = g1W[i];
    if (threadIdx.x < 128) sEnc[threadIdx.x] = encW[threadIdx.x];
    if (threadIdx.x < 64) {
        sEb[threadIdx.x] = encb[threadIdx.x];
        sAs[threadIdx.x] = g1as[threadIdx.x];
        sAd[threadIdx.x] = g1ad[threadIdx.x];
    }
    __syncthreads();
    int node = blockIdx.x * blockDim.x + threadIdx.x;
    if (node >= n) return;

    float x0 = x[node * 2], x1 = x[node * 2 + 1];
    ull acc[32];
#pragma unroll
    for (int i = 0; i < 32; i++) acc[i] = 0ULL;
#pragma unroll 4
    for (int k = 0; k < 64; k++) {
        float h0k = fmaf(x0, sEnc[k], fmaf(x1, sEnc[64 + k], sEb[k]));
        ull hv = pack2(h0k);
        const ulonglong2* wr = (const ulonglong2*)&sW[k * 64];
#pragma unroll
        for (int c8 = 0; c8 < 16; c8++) {
            ulonglong2 w = wr[c8];
            fma2(acc[2 * c8], hv, w.x);
            fma2(acc[2 * c8 + 1], hv, w.y);
        }
    }
    float hp[64];
#pragma unroll
    for (int i = 0; i < 32; i++) {
        float2 f = unpack2(acc[i]);
        hp[2 * i] = f.x; hp[2 * i + 1] = f.y;
    }
    float asv[4] = {0, 0, 0, 0}, adv[4] = {0, 0, 0, 0};
#pragma unroll
    for (int c = 0; c < 64; c++) {
        asv[c >> 4] = fmaf(hp[c], sAs[c], asv[c >> 4]);
        adv[c >> 4] = fmaf(hp[c], sAd[c], adv[c >> 4]);
    }
    float es[4];
#pragma unroll
    for (int h = 0; h < 4; h++) {
        g_as1[node * 4 + h] = asv[h];
        g_ad1[node * 4 + h] = adv[h];
        es[h] = __expf(lrelu(asv[h] + adv[h], 0.2f));
    }
    *(float4*)&g_asum1[node * 4] = make_float4(es[0], es[1], es[2], es[3]);
#pragma unroll
    for (int q = 0; q < 8; q++) {
        int c = q * 8;
        uint4 u = make_uint4(h2bits(hp[c], hp[c + 1]), h2bits(hp[c + 2], hp[c + 3]),
                             h2bits(hp[c + 4], hp[c + 5]), h2bits(hp[c + 6], hp[c + 7]));
        *(uint4*)&g_hp1h[node * 32 + q * 4] = u;
        float e0 = es[c >> 4];
        *(float4*)&g_out1[node * 64 + c] =
            make_float4(hp[c] * e0, hp[c + 1] * e0, hp[c + 2] * e0, hp[c + 3] * e0);
        *(float4*)&g_out1[node * 64 + c + 4] =
            make_float4(hp[c + 4] * e0, hp[c + 5] * e0, hp[c + 6] * e0, hp[c + 7] * e0);
    }
}

// ==================== kernel: gat1 gather (warp/node, fp16 features) =========
__global__ void k_msg1(int n) {
    int warp = (blockIdx.x * blockDim.x + threadIdx.x) >> 5;
    if (warp >= n) return;
    int node = warp;
    int lane = threadIdx.x & 31;
    int beg = g_offs[node], end = g_offs[node + 1];

    float adh = g_ad1[node * 4 + (lane & 3)];
    float2 acc = *(const float2*)&g_out1[node * 64 + lane * 2];
    float wsum = 0.f;

    for (int i = beg; i < end; i += 8) {
        int idx = i + (lane >> 2);
        int2 ce = (idx < end) ? g_csr[idx] : make_int2(node, 0);
        float a = g_as1[ce.x * 4 + (lane & 3)] + adh;
        float w8 = (idx < end) ? __expf(lrelu(a, 0.2f)) : 0.f;
        wsum += w8;
        int m = min(8, end - i);
        for (int k = 0; k < m; k++) {
            int   s  = __shfl_sync(0xffffffffu, ce.x, k * 4);
            float wl = __shfl_sync(0xffffffffu, w8, k * 4 + (lane >> 3));
            unsigned int hb = g_hp1h[s * 32 + lane];
            float2 v = __half22float2(*(__half2*)&hb);
            acc.x = fmaf(wl, v.x, acc.x);
            acc.y = fmaf(wl, v.y, acc.y);
        }
    }
    *(float2*)&g_out1[node * 64 + lane * 2] = acc;
    wsum += __shfl_xor_sync(0xffffffffu, wsum, 4);
    wsum += __shfl_xor_sync(0xffffffffu, wsum, 8);
    wsum += __shfl_xor_sync(0xffffffffu, wsum, 16);
    if (lane < 4) g_asum1[node * 4 + lane] += wsum;
}

// ==================== kernel: finish gat1 + gat2 projection (FFMA2) ==========
__global__ void k_fin1_gat2(const float* __restrict__ g1b,
                            const float* __restrict__ g2W,
                            const float* __restrict__ g2as, const float* __restrict__ g2ad,
                            int n) {
    __shared__ __align__(16) float sW[64 * 64];
    __shared__ __align__(16) float sB[64], sAs[64], sAd[64];
    for (int i = threadIdx.x; i < 4096; i += blockDim.x) sW[i] = g2W[i];
    if (threadIdx.x < 64) {
        sB[threadIdx.x] = g1b[threadIdx.x];
        sAs[threadIdx.x] = g2as[threadIdx.x];
        sAd[threadIdx.x] = g2ad[threadIdx.x];
    }
    __syncthreads();
    int node = blockIdx.x * blockDim.x + threadIdx.x;
    if (node >= n) return;

    float inv[4];
#pragma unroll
    for (int h = 0; h < 4; h++) inv[h] = 1.0f / g_asum1[node * 4 + h];

    ull acc[32];
#pragma unroll
    for (int i = 0; i < 32; i++) acc[i] = 0ULL;
#pragma unroll 2
    for (int k4 = 0; k4 < 16; k4++) {
        float4 o = *(const float4*)&g_out1[node * 64 + k4 * 4];
        float iv = inv[k4 >> 2];
        float hv4[4];
        hv4[0] = o.x * iv + sB[k4 * 4];
        hv4[1] = o.y * iv + sB[k4 * 4 + 1];
        hv4[2] = o.z * iv + sB[k4 * 4 + 2];
        hv4[3] = o.w * iv + sB[k4 * 4 + 3];
#pragma unroll
        for (int j = 0; j < 4; j++) {
            float hj = hv4[j] > 0.f ? hv4[j] : expm1f(hv4[j]);
            ull hv = pack2(hj);
            const ulonglong2* wr = (const ulonglong2*)&sW[(k4 * 4 + j) * 64];
#pragma unroll
            for (int c8 = 0; c8 < 16; c8++) {
                ulonglong2 w = wr[c8];
                fma2(acc[2 * c8], hv, w.x);
                fma2(acc[2 * c8 + 1], hv, w.y);
            }
        }
    }
    float hp[64];
#pragma unroll
    for (int i = 0; i < 32; i++) {
        float2 f = unpack2(acc[i]);
        hp[2 * i] = f.x; hp[2 * i + 1] = f.y;
    }
    float as = 0.f, ad = 0.f;
#pragma unroll
    for (int c = 0; c < 64; c++) {
        as = fmaf(hp[c], sAs[c], as);
        ad = fmaf(hp[c], sAd[c], ad);
    }
    g_as2[node] = as;
    g_ad2[node] = ad;
    float es = __expf(lrelu(as + ad, 0.2f));
    g_asum2[node] = es;
#pragma unroll
    for (int q = 0; q < 8; q++) {
        int c = q * 8;
        uint4 u = make_uint4(h2bits(hp[c], hp[c + 1]), h2bits(hp[c + 2], hp[c + 3]),
                             h2bits(hp[c + 4], hp[c + 5]), h2bits(hp[c + 6], hp[c + 7]));
        *(uint4*)&g_hp2h[node * 32 + q * 4] = u;
        *(float4*)&g_out2[node * 64 + c] =
            make_float4(hp[c] * es, hp[c + 1] * es, hp[c + 2] * es, hp[c + 3] * es);
        *(float4*)&g_out2[node * 64 + c + 4] =
            make_float4(hp[c + 4] * es, hp[c + 5] * es, hp[c + 6] * es, hp[c + 7] * es);
    }
}

// ==================== kernel: gat2 gather (warp/node, fp16 features) =========
__global__ void k_msg2(int n) {
    int warp = (blockIdx.x * blockDim.x + threadIdx.x) >> 5;
    if (warp >= n) return;
    int node = warp;
    int lane = threadIdx.x & 31;
    int beg = g_offs[node], end = g_offs[node + 1];

    float ad2 = g_ad2[node];
    float2 acc = *(const float2*)&g_out2[node * 64 + lane * 2];
    float wsum = 0.f;

    for (int i = beg; i < end; i += 32) {
        int idx = i + lane;
        int2 ce = (idx < end) ? g_csr[idx] : make_int2(node, 0);
        float a = g_as2[ce.x] + ad2;
        float w32 = (idx < end) ? __expf(lrelu(a, 0.2f)) : 0.f;
        wsum += w32;
        int m = min(32, end - i);
        for (int k = 0; k < m; k++) {
            int   s  = __shfl_sync(0xffffffffu, ce.x, k);
            float wl = __shfl_sync(0xffffffffu, w32, k);
            unsigned int hb = g_hp2h[s * 32 + lane];
            float2 v = __half22float2(*(__half2*)&hb);
            acc.x = fmaf(wl, v.x, acc.x);
            acc.y = fmaf(wl, v.y, acc.y);
        }
    }
    *(float2*)&g_out2[node * 64 + lane * 2] = acc;
    wsum += __shfl_xor_sync(0xffffffffu, wsum, 16);
    wsum += __shfl_xor_sync(0xffffffffu, wsum, 8);
    wsum += __shfl_xor_sync(0xffffffffu, wsum, 4);
    wsum += __shfl_xor_sync(0xffffffffu, wsum, 2);
    wsum += __shfl_xor_sync(0xffffffffu, wsum, 1);
    if (lane == 0) g_asum2[node] += wsum;
}

// ==================== kernel: finish gat2 + EA/EB + node head (FFMA2) ========
__global__ void k_fin2_heads(const float* __restrict__ g2b,
                             const float* __restrict__ eoW1, const float* __restrict__ eob1,
                             const float* __restrict__ noW1, const float* __restrict__ nob1,
                             const float* __restrict__ noW2, const float* __restrict__ nob2,
                             float* __restrict__ out, int n, int e) {
    __shared__ __align__(16) float sWa[64 * 64];
    __shared__ __align__(16) float sWb[64 * 64];
    __shared__ __align__(16) float sWn[64 * 64];
    __shared__ __align__(16) float sB[64], sB1[64], sBn[64], sW2[128];
    for (int i = threadIdx.x; i < 4096; i += blockDim.x) {
        sWa[i] = eoW1[i];
        sWb[i] = eoW1[4096 + i];
        sWn[i] = noW1[i];
    }
    if (threadIdx.x < 64) {
        sB[threadIdx.x]  = g2b[threadIdx.x];
        sB1[threadIdx.x] = eob1[threadIdx.x];
        sBn[threadIdx.x] = nob1[threadIdx.x];
    }
    if (threadIdx.x < 128) sW2[threadIdx.x] = noW2[threadIdx.x];
    __syncthreads();
    int node = blockIdx.x * blockDim.x + threadIdx.x;
    if (node >= n) return;

    float inv = 1.0f / g_asum2[node];
    float h2[64];
#pragma unroll
    for (int c4 = 0; c4 < 16; c4++) {
        float4 o = *(const float4*)&g_out2[node * 64 + c4 * 4];
        h2[c4 * 4]     = o.x * inv + sB[c4 * 4];
        h2[c4 * 4 + 1] = o.y * inv + sB[c4 * 4 + 1];
        h2[c4 * 4 + 2] = o.z * inv + sB[c4 * 4 + 2];
        h2[c4 * 4 + 3] = o.w * inv + sB[c4 * 4 + 3];
    }

    ull acc[32];
    // ---- GEMM A: EA = h2 @ Wa + b1  (stored fp16) ----
#pragma unroll
    for (int i = 0; i < 32; i++) acc[i] = 0ULL;
#pragma unroll 4
    for (int k = 0; k < 64; k++) {
        ull hv = pack2(h2[k]);
        const ulonglong2* wr = (const ulonglong2*)&sWa[k * 64];
#pragma unroll
        for (int c8 = 0; c8 < 16; c8++) {
            ulonglong2 w = wr[c8];
            fma2(acc[2 * c8], hv, w.x);
            fma2(acc[2 * c8 + 1], hv, w.y);
        }
    }
#pragma unroll
    for (int q = 0; q < 8; q++) {
        float2 f0 = unpack2(acc[q * 4]),     f1 = unpack2(acc[q * 4 + 1]);
        float2 f2 = unpack2(acc[q * 4 + 2]), f3 = unpack2(acc[q * 4 + 3]);
        int c = q * 8;
        uint4 u = make_uint4(h2bits(f0.x + sB1[c], f0.y + sB1[c + 1]),
                             h2bits(f1.x + sB1[c + 2], f1.y + sB1[c + 3]),
                             h2bits(f2.x + sB1[c + 4], f2.y + sB1[c + 5]),
                             h2bits(f3.x + sB1[c + 6], f3.y + sB1[c + 7]));
        *(uint4*)&g_EAh[node * 32 + q * 4] = u;
    }
    // ---- GEMM B: EB = h2 @ Wb  (fp32) ----
#pragma unroll
    for (int i = 0; i < 32; i++) acc[i] = 0ULL;
#pragma unroll 4
    for (int k = 0; k < 64; k++) {
        ull hv = pack2(h2[k]);
        const ulonglong2* wr = (const ulonglong2*)&sWb[k * 64];
#pragma unroll
        for (int c8 = 0; c8 < 16; c8++) {
            ulonglong2 w = wr[c8];
            fma2(acc[2 * c8], hv, w.x);
            fma2(acc[2 * c8 + 1], hv, w.y);
        }
    }
#pragma unroll
    for (int q = 0; q < 16; q++) {
        float2 f0 = unpack2(acc[q * 2]), f1 = unpack2(acc[q * 2 + 1]);
        *(float4*)&g_EB[node * 64 + q * 4] = make_float4(f0.x, f0.y, f1.x, f1.y);
    }
    // ---- GEMM N: node head ----
#pragma unroll
    for (int i = 0; i < 32; i++) acc[i] = 0ULL;
#pragma unroll 4
    for (int k = 0; k < 64; k++) {
        ull hv = pack2(h2[k]);
        const ulonglong2* wr = (const ulonglong2*)&sWn[k * 64];
#pragma unroll
        for (int c8 = 0; c8 < 16; c8++) {
            ulonglong2 w = wr[c8];
            fma2(acc[2 * c8], hv, w.x);
            fma2(acc[2 * c8 + 1], hv, w.y);
        }
    }
    float p0 = 0.f, p1 = 0.f;
#pragma unroll
    for (int i = 0; i < 32; i++) {
        float2 f = unpack2(acc[i]);
        float t0 = lrelu(f.x + sBn[2 * i], 0.01f);
        float t1 = lrelu(f.y + sBn[2 * i + 1], 0.01f);
        p0 = fmaf(t0, sW2[4 * i],     fmaf(t1, sW2[4 * i + 2], p0));
        p1 = fmaf(t0, sW2[4 * i + 1], fmaf(t1, sW2[4 * i + 3], p1));
    }
    out[e + node * 2]     = tanhf(p0 + nob2[0]);
    out[e + node * 2 + 1] = tanhf(p1 + nob2[1]);
}

// ==================== kernel: edge head (warp/node, fp16 EA) =================
__global__ void k_edgehead(const float* __restrict__ eattr,
                           const float* __restrict__ eoW1,
                           const float* __restrict__ eoW2, const float* __restrict__ eob2,
                           float* __restrict__ out, int n) {
    int warp = (blockIdx.x * blockDim.x + threadIdx.x) >> 5;
    if (warp >= n) return;
    int node = warp;
    int lane = threadIdx.x & 31;
    int beg = g_offs[node], end = g_offs[node + 1];
    if (beg == end) return;

    float2 w128 = *(const float2*)&eoW1[128 * 64 + lane * 2];
    float2 w129 = *(const float2*)&eoW1[129 * 64 + lane * 2];
    float2 w2   = *(const float2*)&eoW2[lane * 2];
    float  b2   = eob2[0];
    float2 eb   = *(const float2*)&g_EB[node * 64 + lane * 2];

    for (int i = beg; i < end; i += 32) {
        int idx = i + lane;
        int2 ce = (idx < end) ? g_csr[idx] : make_int2(node, 0);
        float2 ea = *(const float2*)&eattr[ce.y * 2];
        int m = min(32, end - i);
        for (int k = 0; k < m; k++) {
            int   s   = __shfl_sync(0xffffffffu, ce.x, k);
            int   eid = __shfl_sync(0xffffffffu, ce.y, k);
            float ea0 = __shfl_sync(0xffffffffu, ea.x, k);
            float ea1 = __shfl_sync(0xffffffffu, ea.y, k);
            unsigned int vb = g_EAh[s * 32 + lane];
            float2 va = __half22float2(*(__half2*)&vb);
            float pre0 = va.x + eb.x + ea0 * w128.x + ea1 * w129.x;
            float pre1 = va.y + eb.y + ea0 * w128.y + ea1 * w129.y;
            float p = lrelu(pre0, 0.01f) * w2.x + lrelu(pre1, 0.01f) * w2.y;
            p += __shfl_xor_sync(0xffffffffu, p, 16);
            p += __shfl_xor_sync(0xffffffffu, p, 8);
            p += __shfl_xor_sync(0xffffffffu, p, 4);
            p += __shfl_xor_sync(0xffffffffu, p, 2);
            p += __shfl_xor_sync(0xffffffffu, p, 1);
            if (lane == 0) out[eid] = tanhf(p + b2);
        }
    }
}

// ==================== launch ==================================================
extern "C" void kernel_launch(void* const* d_in, const int* in_sizes, int n_in,
                              void* d_out, int out_size) {
    const float* x      = (const float*)d_in[0];
    const int*   eidx   = (const int*)d_in[1];
    const float* eattr  = (const float*)d_in[2];
    const float* encW   = (const float*)d_in[3];
    const float* encb   = (const float*)d_in[4];
    const float* g1W    = (const float*)d_in[5];
    const float* g1as   = (const float*)d_in[6];
    const float* g1ad   = (const float*)d_in[7];
    const float* g1b    = (const float*)d_in[8];
    const float* g2W    = (const float*)d_in[9];
    const float* g2as   = (const float*)d_in[10];
    const float* g2ad   = (const float*)d_in[11];
    const float* g2b    = (const float*)d_in[12];
    const float* noW1   = (const float*)d_in[13];
    const float* nob1   = (const float*)d_in[14];
    const float* noW2   = (const float*)d_in[15];
    const float* nob2   = (const float*)d_in[16];
    const float* eoW1   = (const float*)d_in[17];
    const float* eob1   = (const float*)d_in[18];
    const float* eoW2   = (const float*)d_in[19];
    const float* eob2   = (const float*)d_in[20];
    float* out = (float*)d_out;

    int n = in_sizes[0] / 2;
    int e = in_sizes[1] / 2;
    const int* src = eidx;
    const int* dst = eidx + e;

    const int B = 256;
    int gn = (n + B - 1) / B;
    int ge = (e + B - 1) / B;
    int gw = (n * 32 + B - 1) / B;

    // CSR build (dst-sorted)
    k_zero<<<gn, B>>>(n);
    k_hist<<<ge, B>>>(dst, e);
    k_chunksum<<<NCHUNK, 256>>>(n);
    k_scanchunk<<<1, NCHUNK>>>();
    k_scanwrite<<<NCHUNK, 1024>>>(n);
    k_scatter<<<ge, B>>>(src, dst, e);

    // pipeline
    k_enc_gat1<<<gn, B>>>(x, encW, encb, g1W, g1as, g1ad, n);
    k_msg1<<<gw, B>>>(n);
    k_fin1_gat2<<<gn, B>>>(g1b, g2W, g2as, g2ad, n);
    k_msg2<<<gw, B>>>(n);
    k_fin2_heads<<<gn, B>>>(g2b, eoW1, eob1, noW1, nob1, noW2, nob2, out, n, e);
    k_edgehead<<<gw, B>>>(eattr, eoW1, eoW2, eob2, out, n);
}

// round 6
// speedup vs baseline: 1.7881x; 1.1847x over previous
#include <cuda_runtime.h>
#include <cuda_fp16.h>

#define NN 100000
#define EE 1600000
#define NCHUNK 128
#define CH 782   // ceil(100000/128)

// ---------------- scratch (static device globals) ----------------------------
__device__ unsigned int g_hp1h[NN * 32];   // half2 bit patterns, 64ch/node
__device__ float g_out1[NN * 64];
__device__ float g_as1[NN * 4];
__device__ float g_ad1[NN * 4];
__device__ float g_asum1[NN * 4];
__device__ unsigned int g_hp2h[NN * 32];
__device__ float g_out2[NN * 64];
__device__ float g_as2[NN];
__device__ float g_ad2[NN];
__device__ float g_asum2[NN];
__device__ unsigned int g_EAh[NN * 32];    // fp16 EA
__device__ float g_EB[NN * 64];
// rank-2 encoder precompute
__device__ float g_P0[64], g_P1[64], g_Pb[64];
// CSR build
__device__ int  g_cnt[NN];
__device__ int  g_offs[NN + 1];
__device__ int  g_cur[NN];
__device__ int2 g_csr[EE];                 // .x = src node, .y = edge id
__device__ int  g_bsum[NCHUNK];
__device__ int  g_boff[NCHUNK];

// ---------------- helpers ----------------------------------------------------
__device__ __forceinline__ float lrelu(float x, float s) { return x > 0.f ? x : s * x; }

typedef unsigned long long ull;
__device__ __forceinline__ ull pack2(float v) {
    ull r;
    unsigned int u = __float_as_uint(v);
    asm("mov.b64 %0, {%1, %1};" : "=l"(r) : "r"(u));
    return r;
}
__device__ __forceinline__ void fma2(ull& d, ull a, ull b) {
    asm("fma.rn.f32x2 %0, %1, %2, %3;" : "=l"(d) : "l"(a), "l"(b), "l"(d));
}
__device__ __forceinline__ float2 unpack2(ull v) {
    unsigned int lo, hi;
    asm("mov.b64 {%0, %1}, %2;" : "=r"(lo), "=r"(hi) : "l"(v));
    return make_float2(__uint_as_float(lo), __uint_as_float(hi));
}
__device__ __forceinline__ unsigned int h2bits(float a, float b) {
    __half2 h = __floats2half2_rn(a, b);
    return *(unsigned int*)&h;
}
__device__ __forceinline__ float2 h2f2(unsigned int b) {
    return __half22float2(*(__half2*)&b);
}

// ==================== CSR build ==============================================
__global__ void k_zero(int n) {
    int t = blockIdx.x * blockDim.x + threadIdx.x;
    if (t < n) g_cnt[t] = 0;
}
__global__ void k_hist(const int* __restrict__ dst, int e) {
    int t = blockIdx.x * blockDim.x + threadIdx.x;
    if (t < e) atomicAdd(&g_cnt[dst[t]], 1);
}
__global__ void k_chunksum(int n) {
    __shared__ int red[256];
    int b = blockIdx.x, t = threadIdx.x;
    int base = b * CH;
    int s = 0;
    for (int i = t; i < CH; i += 256)
        if (base + i < n) s += g_cnt[base + i];
    red[t] = s; __syncthreads();
    for (int o = 128; o > 0; o >>= 1) {
        if (t < o) red[t] += red[t + o];
        __syncthreads();
    }
    if (t == 0) g_bsum[b] = red[0];
}
__global__ void k_scanchunk() {
    __shared__ int sd[NCHUNK];
    int t = threadIdx.x;
    int v = g_bsum[t];
    sd[t] = v; __syncthreads();
    for (int o = 1; o < NCHUNK; o <<= 1) {
        int x = (t >= o) ? sd[t - o] : 0;
        __syncthreads();
        sd[t] += x;
        __syncthreads();
    }
    g_boff[t] = sd[t] - v;
}
__global__ void k_scanwrite(int n) {
    __shared__ int sd[1024];
    int b = blockIdx.x, t = threadIdx.x;
    int base = b * CH;
    int v = (t < CH && base + t < n) ? g_cnt[base + t] : 0;
    sd[t] = v; __syncthreads();
    for (int o = 1; o < 1024; o <<= 1) {
        int x = (t >= o) ? sd[t - o] : 0;
        __syncthreads();
        sd[t] += x;
        __syncthreads();
    }
    int excl = sd[t] - v + g_boff[b];
    if (t < CH && base + t < n) { g_offs[base + t] = excl; g_cur[base + t] = excl; }
    if (base + t == n - 1) g_offs[n] = excl + v;
}
__global__ void k_scatter(const int* __restrict__ src, const int* __restrict__ dst, int e) {
    int t = blockIdx.x * blockDim.x + threadIdx.x;
    if (t >= e) return;
    int d = dst[t];
    int pos = atomicAdd(&g_cur[d], 1);
    g_csr[pos] = make_int2(src[t], t);
}

// ==================== kernel: rank-2 encoder precompute ======================
// P0 = encW_row0 @ g1W ; P1 = encW_row1 @ g1W ; Pb = encb @ g1W
__global__ void k_pre(const float* __restrict__ encW, const float* __restrict__ encb,
                      const float* __restrict__ g1W) {
    int c = threadIdx.x;           // 64 threads
    float p0 = 0.f, p1 = 0.f, pb = 0.f;
    for (int k = 0; k < 64; k++) {
        float w = g1W[k * 64 + c];
        p0 = fmaf(encW[k], w, p0);
        p1 = fmaf(encW[64 + k], w, p1);
        pb = fmaf(encb[k], w, pb);
    }
    g_P0[c] = p0; g_P1[c] = p1; g_Pb[c] = pb;
}

// ==================== kernel: encoder+gat1 projection (rank-2) ===============
__global__ void k_enc_gat1(const float* __restrict__ x,
                           const float* __restrict__ g1as, const float* __restrict__ g1ad,
                           int n) {
    __shared__ __align__(16) float sP0[64], sP1[64], sPb[64], sAs[64], sAd[64];
    if (threadIdx.x < 64) {
        sP0[threadIdx.x] = g_P0[threadIdx.x];
        sP1[threadIdx.x] = g_P1[threadIdx.x];
        sPb[threadIdx.x] = g_Pb[threadIdx.x];
        sAs[threadIdx.x] = g1as[threadIdx.x];
        sAd[threadIdx.x] = g1ad[threadIdx.x];
    }
    __syncthreads();
    int node = blockIdx.x * blockDim.x + threadIdx.x;
    if (node >= n) return;

    float2 xv = *(const float2*)&x[node * 2];
    float hp[64];
    float asv[4] = {0, 0, 0, 0}, adv[4] = {0, 0, 0, 0};
#pragma unroll
    for (int c = 0; c < 64; c++) {
        float v = fmaf(xv.x, sP0[c], fmaf(xv.y, sP1[c], sPb[c]));
        hp[c] = v;
        asv[c >> 4] = fmaf(v, sAs[c], asv[c >> 4]);
        adv[c >> 4] = fmaf(v, sAd[c], adv[c >> 4]);
    }
    float es[4];
#pragma unroll
    for (int h = 0; h < 4; h++) {
        g_as1[node * 4 + h] = asv[h];
        g_ad1[node * 4 + h] = adv[h];
        es[h] = __expf(lrelu(asv[h] + adv[h], 0.2f));
    }
    *(float4*)&g_asum1[node * 4] = make_float4(es[0], es[1], es[2], es[3]);
#pragma unroll
    for (int q = 0; q < 8; q++) {
        int c = q * 8;
        uint4 u = make_uint4(h2bits(hp[c], hp[c + 1]), h2bits(hp[c + 2], hp[c + 3]),
                             h2bits(hp[c + 4], hp[c + 5]), h2bits(hp[c + 6], hp[c + 7]));
        *(uint4*)&g_hp1h[node * 32 + q * 4] = u;
        float e0 = es[c >> 4];
        *(float4*)&g_out1[node * 64 + c] =
            make_float4(hp[c] * e0, hp[c + 1] * e0, hp[c + 2] * e0, hp[c + 3] * e0);
        *(float4*)&g_out1[node * 64 + c + 4] =
            make_float4(hp[c + 4] * e0, hp[c + 5] * e0, hp[c + 6] * e0, hp[c + 7] * e0);
    }
}

// ==================== kernel: gat1 gather (warp/node, unrolled MLP=8) ========
__global__ void k_msg1(int n) {
    int warp = (blockIdx.x * blockDim.x + threadIdx.x) >> 5;
    if (warp >= n) return;
    int node = warp;
    int lane = threadIdx.x & 31;
    int beg = g_offs[node], end = g_offs[node + 1];

    float adh = g_ad1[node * 4 + (lane & 3)];
    float2 acc = *(const float2*)&g_out1[node * 64 + lane * 2];
    float wsum = 0.f;

    for (int i = beg; i < end; i += 8) {
        int idx = i + (lane >> 2);                // 8 edges, 4 lanes each
        int2 ce = (idx < end) ? g_csr[idx] : make_int2(node, 0);
        float a = g_as1[ce.x * 4 + (lane & 3)] + adh;
        float w8 = (idx < end) ? __expf(lrelu(a, 0.2f)) : 0.f;
        wsum += w8;
        int ss[8];
#pragma unroll
        for (int k = 0; k < 8; k++) ss[k] = __shfl_sync(0xffffffffu, ce.x, k * 4);
        float2 vv[8];
#pragma unroll
        for (int k = 0; k < 8; k++) vv[k] = h2f2(g_hp1h[ss[k] * 32 + lane]);
#pragma unroll
        for (int k = 0; k < 8; k++) {
            float wl = __shfl_sync(0xffffffffu, w8, k * 4 + (lane >> 3));
            acc.x = fmaf(wl, vv[k].x, acc.x);
            acc.y = fmaf(wl, vv[k].y, acc.y);
        }
    }
    *(float2*)&g_out1[node * 64 + lane * 2] = acc;
    wsum += __shfl_xor_sync(0xffffffffu, wsum, 4);
    wsum += __shfl_xor_sync(0xffffffffu, wsum, 8);
    wsum += __shfl_xor_sync(0xffffffffu, wsum, 16);
    if (lane < 4) g_asum1[node * 4 + lane] += wsum;
}

// ==================== kernel: finish gat1 + gat2 projection (FFMA2) ==========
__global__ void k_fin1_gat2(const float* __restrict__ g1b,
                            const float* __restrict__ g2W,
                            const float* __restrict__ g2as, const float* __restrict__ g2ad,
                            int n) {
    __shared__ __align__(16) float sW[64 * 64];
    __shared__ __align__(16) float sB[64], sAs[64], sAd[64];
    for (int i = threadIdx.x; i < 4096; i += blockDim.x) sW[i] = g2W[i];
    if (threadIdx.x < 64) {
        sB[threadIdx.x] = g1b[threadIdx.x];
        sAs[threadIdx.x] = g2as[threadIdx.x];
        sAd[threadIdx.x] = g2ad[threadIdx.x];
    }
    __syncthreads();
    int node = blockIdx.x * blockDim.x + threadIdx.x;
    if (node >= n) return;

    float inv[4];
#pragma unroll
    for (int h = 0; h < 4; h++) inv[h] = 1.0f / g_asum1[node * 4 + h];

    ull acc[32];
#pragma unroll
    for (int i = 0; i < 32; i++) acc[i] = 0ULL;
#pragma unroll 2
    for (int k4 = 0; k4 < 16; k4++) {
        float4 o = *(const float4*)&g_out1[node * 64 + k4 * 4];
        float iv = inv[k4 >> 2];
        float hv4[4];
        hv4[0] = o.x * iv + sB[k4 * 4];
        hv4[1] = o.y * iv + sB[k4 * 4 + 1];
        hv4[2] = o.z * iv + sB[k4 * 4 + 2];
        hv4[3] = o.w * iv + sB[k4 * 4 + 3];
#pragma unroll
        for (int j = 0; j < 4; j++) {
            float hj = hv4[j] > 0.f ? hv4[j] : expm1f(hv4[j]);
            ull hv = pack2(hj);
            const ulonglong2* wr = (const ulonglong2*)&sW[(k4 * 4 + j) * 64];
#pragma unroll
            for (int c8 = 0; c8 < 16; c8++) {
                ulonglong2 w = wr[c8];
                fma2(acc[2 * c8], hv, w.x);
                fma2(acc[2 * c8 + 1], hv, w.y);
            }
        }
    }
    float hp[64];
#pragma unroll
    for (int i = 0; i < 32; i++) {
        float2 f = unpack2(acc[i]);
        hp[2 * i] = f.x; hp[2 * i + 1] = f.y;
    }
    float as = 0.f, ad = 0.f;
#pragma unroll
    for (int c = 0; c < 64; c++) {
        as = fmaf(hp[c], sAs[c], as);
        ad = fmaf(hp[c], sAd[c], ad);
    }
    g_as2[node] = as;
    g_ad2[node] = ad;
    float es = __expf(lrelu(as + ad, 0.2f));
    g_asum2[node] = es;
#pragma unroll
    for (int q = 0; q < 8; q++) {
        int c = q * 8;
        uint4 u = make_uint4(h2bits(hp[c], hp[c + 1]), h2bits(hp[c + 2], hp[c + 3]),
                             h2bits(hp[c + 4], hp[c + 5]), h2bits(hp[c + 6], hp[c + 7]));
        *(uint4*)&g_hp2h[node * 32 + q * 4] = u;
        *(float4*)&g_out2[node * 64 + c] =
            make_float4(hp[c] * es, hp[c + 1] * es, hp[c + 2] * es, hp[c + 3] * es);
        *(float4*)&g_out2[node * 64 + c + 4] =
            make_float4(hp[c + 4] * es, hp[c + 5] * es, hp[c + 6] * es, hp[c + 7] * es);
    }
}

// ==================== kernel: gat2 gather (warp/node, unrolled MLP=8) ========
__global__ void k_msg2(int n) {
    int warp = (blockIdx.x * blockDim.x + threadIdx.x) >> 5;
    if (warp >= n) return;
    int node = warp;
    int lane = threadIdx.x & 31;
    int beg = g_offs[node], end = g_offs[node + 1];

    float ad2 = g_ad2[node];
    float2 acc = *(const float2*)&g_out2[node * 64 + lane * 2];
    float wsum = 0.f;

    for (int i = beg; i < end; i += 32) {
        int idx = i + lane;
        int2 ce = (idx < end) ? g_csr[idx] : make_int2(node, 0);
        float a = g_as2[ce.x] + ad2;
        float w32 = (idx < end) ? __expf(lrelu(a, 0.2f)) : 0.f;
        wsum += w32;
#pragma unroll
        for (int kk = 0; kk < 4; kk++) {
            if (i + kk * 8 >= end) break;
            int ss[8];
#pragma unroll
            for (int k = 0; k < 8; k++) ss[k] = __shfl_sync(0xffffffffu, ce.x, kk * 8 + k);
            float2 vv[8];
#pragma unroll
            for (int k = 0; k < 8; k++) vv[k] = h2f2(g_hp2h[ss[k] * 32 + lane]);
#pragma unroll
            for (int k = 0; k < 8; k++) {
                float wl = __shfl_sync(0xffffffffu, w32, kk * 8 + k);
                acc.x = fmaf(wl, vv[k].x, acc.x);
                acc.y = fmaf(wl, vv[k].y, acc.y);
            }
        }
    }
    *(float2*)&g_out2[node * 64 + lane * 2] = acc;
    wsum += __shfl_xor_sync(0xffffffffu, wsum, 16);
    wsum += __shfl_xor_sync(0xffffffffu, wsum, 8);
    wsum += __shfl_xor_sync(0xffffffffu, wsum, 4);
    wsum += __shfl_xor_sync(0xffffffffu, wsum, 2);
    wsum += __shfl_xor_sync(0xffffffffu, wsum, 1);
    if (lane == 0) g_asum2[node] += wsum;
}

// ==================== kernel: finish gat2 + EA/EB + node head (FFMA2) ========
__global__ void k_fin2_heads(const float* __restrict__ g2b,
                             const float* __restrict__ eoW1, const float* __restrict__ eob1,
                             const float* __restrict__ noW1, const float* __restrict__ nob1,
                             const float* __restrict__ noW2, const float* __restrict__ nob2,
                             float* __restrict__ out, int n, int e) {
    __shared__ __align__(16) float sWa[64 * 64];
    __shared__ __align__(16) float sWb[64 * 64];
    __shared__ __align__(16) float sWn[64 * 64];
    __shared__ __align__(16) float sB[64], sB1[64], sBn[64], sW2[128];
    for (int i = threadIdx.x; i < 4096; i += blockDim.x) {
        sWa[i] = eoW1[i];
        sWb[i] = eoW1[4096 + i];
        sWn[i] = noW1[i];
    }
    if (threadIdx.x < 64) {
        sB[threadIdx.x]  = g2b[threadIdx.x];
        sB1[threadIdx.x] = eob1[threadIdx.x];
        sBn[threadIdx.x] = nob1[threadIdx.x];
    }
    if (threadIdx.x < 128) sW2[threadIdx.x] = noW2[threadIdx.x];
    __syncthreads();
    int node = blockIdx.x * blockDim.x + threadIdx.x;
    if (node >= n) return;

    float inv = 1.0f / g_asum2[node];
    float h2[64];
#pragma unroll
    for (int c4 = 0; c4 < 16; c4++) {
        float4 o = *(const float4*)&g_out2[node * 64 + c4 * 4];
        h2[c4 * 4]     = o.x * inv + sB[c4 * 4];
        h2[c4 * 4 + 1] = o.y * inv + sB[c4 * 4 + 1];
        h2[c4 * 4 + 2] = o.z * inv + sB[c4 * 4 + 2];
        h2[c4 * 4 + 3] = o.w * inv + sB[c4 * 4 + 3];
    }

    ull acc[32];
    // ---- EA = h2 @ Wa + b1 (fp16 store) ----
#pragma unroll
    for (int i = 0; i < 32; i++) acc[i] = 0ULL;
#pragma unroll 4
    for (int k = 0; k < 64; k++) {
        ull hv = pack2(h2[k]);
        const ulonglong2* wr = (const ulonglong2*)&sWa[k * 64];
#pragma unroll
        for (int c8 = 0; c8 < 16; c8++) {
            ulonglong2 w = wr[c8];
            fma2(acc[2 * c8], hv, w.x);
            fma2(acc[2 * c8 + 1], hv, w.y);
        }
    }
#pragma unroll
    for (int q = 0; q < 8; q++) {
        float2 f0 = unpack2(acc[q * 4]),     f1 = unpack2(acc[q * 4 + 1]);
        float2 f2 = unpack2(acc[q * 4 + 2]), f3 = unpack2(acc[q * 4 + 3]);
        int c = q * 8;
        uint4 u = make_uint4(h2bits(f0.x + sB1[c], f0.y + sB1[c + 1]),
                             h2bits(f1.x + sB1[c + 2], f1.y + sB1[c + 3]),
                             h2bits(f2.x + sB1[c + 4], f2.y + sB1[c + 5]),
                             h2bits(f3.x + sB1[c + 6], f3.y + sB1[c + 7]));
        *(uint4*)&g_EAh[node * 32 + q * 4] = u;
    }
    // ---- EB = h2 @ Wb (fp32) ----
#pragma unroll
    for (int i = 0; i < 32; i++) acc[i] = 0ULL;
#pragma unroll 4
    for (int k = 0; k < 64; k++) {
        ull hv = pack2(h2[k]);
        const ulonglong2* wr = (const ulonglong2*)&sWb[k * 64];
#pragma unroll
        for (int c8 = 0; c8 < 16; c8++) {
            ulonglong2 w = wr[c8];
            fma2(acc[2 * c8], hv, w.x);
            fma2(acc[2 * c8 + 1], hv, w.y);
        }
    }
#pragma unroll
    for (int q = 0; q < 16; q++) {
        float2 f0 = unpack2(acc[q * 2]), f1 = unpack2(acc[q * 2 + 1]);
        *(float4*)&g_EB[node * 64 + q * 4] = make_float4(f0.x, f0.y, f1.x, f1.y);
    }
    // ---- node head ----
#pragma unroll
    for (int i = 0; i < 32; i++) acc[i] = 0ULL;
#pragma unroll 4
    for (int k = 0; k < 64; k++) {
        ull hv = pack2(h2[k]);
        const ulonglong2* wr = (const ulonglong2*)&sWn[k * 64];
#pragma unroll
        for (int c8 = 0; c8 < 16; c8++) {
            ulonglong2 w = wr[c8];
            fma2(acc[2 * c8], hv, w.x);
            fma2(acc[2 * c8 + 1], hv, w.y);
        }
    }
    float p0 = 0.f, p1 = 0.f;
#pragma unroll
    for (int i = 0; i < 32; i++) {
        float2 f = unpack2(acc[i]);
        float t0 = lrelu(f.x + sBn[2 * i], 0.01f);
        float t1 = lrelu(f.y + sBn[2 * i + 1], 0.01f);
        p0 = fmaf(t0, sW2[4 * i],     fmaf(t1, sW2[4 * i + 2], p0));
        p1 = fmaf(t0, sW2[4 * i + 1], fmaf(t1, sW2[4 * i + 3], p1));
    }
    out[e + node * 2]     = tanhf(p0 + nob2[0]);
    out[e + node * 2 + 1] = tanhf(p1 + nob2[1]);
}

// ==================== kernel: edge head (warp/node, unrolled MLP=8) ==========
__global__ void k_edgehead(const float* __restrict__ eattr,
                           const float* __restrict__ eoW1,
                           const float* __restrict__ eoW2, const float* __restrict__ eob2,
                           float* __restrict__ out, int n) {
    int warp = (blockIdx.x * blockDim.x + threadIdx.x) >> 5;
    if (warp >= n) return;
    int node = warp;
    int lane = threadIdx.x & 31;
    int beg = g_offs[node], end = g_offs[node + 1];
    if (beg == end) return;

    float2 w128 = *(const float2*)&eoW1[128 * 64 + lane * 2];
    float2 w129 = *(const float2*)&eoW1[129 * 64 + lane * 2];
    float2 w2   = *(const float2*)&eoW2[lane * 2];
    float  b2   = eob2[0];
    float2 eb   = *(const float2*)&g_EB[node * 64 + lane * 2];

    for (int i = beg; i < end; i += 32) {
        int idx = i + lane;
        int2 ce = (idx < end) ? g_csr[idx] : make_int2(node, 0);
        float2 ea = *(const float2*)&eattr[ce.y * 2];
#pragma unroll
        for (int kk = 0; kk < 4; kk++) {
            if (i + kk * 8 >= end) break;
            int ss[8], ei[8];
            float ex[8], ey[8];
#pragma unroll
            for (int k = 0; k < 8; k++) {
                ss[k] = __shfl_sync(0xffffffffu, ce.x, kk * 8 + k);
                ei[k] = __shfl_sync(0xffffffffu, ce.y, kk * 8 + k);
                ex[k] = __shfl_sync(0xffffffffu, ea.x, kk * 8 + k);
                ey[k] = __shfl_sync(0xffffffffu, ea.y, kk * 8 + k);
            }
            float2 va[8];
#pragma unroll
            for (int k = 0; k < 8; k++) va[k] = h2f2(g_EAh[ss[k] * 32 + lane]);
            float p[8];
#pragma unroll
            for (int k = 0; k < 8; k++) {
                float pre0 = va[k].x + eb.x + ex[k] * w128.x + ey[k] * w129.x;
                float pre1 = va[k].y + eb.y + ex[k] * w128.y + ey[k] * w129.y;
                p[k] = lrelu(pre0, 0.01f) * w2.x + lrelu(pre1, 0.01f) * w2.y;
            }
#pragma unroll
            for (int k = 0; k < 8; k++) {
                p[k] += __shfl_xor_sync(0xffffffffu, p[k], 16);
                p[k] += __shfl_xor_sync(0xffffffffu, p[k], 8);
                p[k] += __shfl_xor_sync(0xffffffffu, p[k], 4);
                p[k] += __shfl_xor_sync(0xffffffffu, p[k], 2);
                p[k] += __shfl_xor_sync(0xffffffffu, p[k], 1);
            }
#pragma unroll
            for (int k = 0; k < 8; k++)
                if (lane == 0 && (i + kk * 8 + k) < end) out[ei[k]] = tanhf(p[k] + b2);
        }
    }
}

// ==================== launch ==================================================
extern "C" void kernel_launch(void* const* d_in, const int* in_sizes, int n_in,
                              void* d_out, int out_size) {
    const float* x      = (const float*)d_in[0];
    const int*   eidx   = (const int*)d_in[1];
    const float* eattr  = (const float*)d_in[2];
    const float* encW   = (const float*)d_in[3];
    const float* encb   = (const float*)d_in[4];
    const float* g1W    = (const float*)d_in[5];
    const float* g1as   = (const float*)d_in[6];
    const float* g1ad   = (const float*)d_in[7];
    const float* g1b    = (const float*)d_in[8];
    const float* g2W    = (const float*)d_in[9];
    const float* g2as   = (const float*)d_in[10];
    const float* g2ad   = (const float*)d_in[11];
    const float* g2b    = (const float*)d_in[12];
    const float* noW1   = (const float*)d_in[13];
    const float* nob1   = (const float*)d_in[14];
    const float* noW2   = (const float*)d_in[15];
    const float* nob2   = (const float*)d_in[16];
    const float* eoW1   = (const float*)d_in[17];
    const float* eob1   = (const float*)d_in[18];
    const float* eoW2   = (const float*)d_in[19];
    const float* eob2   = (const float*)d_in[20];
    float* out = (float*)d_out;

    int n = in_sizes[0] / 2;
    int e = in_sizes[1] / 2;
    const int* src = eidx;
    const int* dst = eidx + e;

    const int B = 256;
    int gn = (n + B - 1) / B;
    int ge = (e + B - 1) / B;
    int gw = (n * 32 + B - 1) / B;

    // CSR build (dst-sorted)
    k_zero<<<gn, B>>>(n);
    k_hist<<<ge, B>>>(dst, e);
    k_chunksum<<<NCHUNK, 256>>>(n);
    k_scanchunk<<<1, NCHUNK>>>();
    k_scanwrite<<<NCHUNK, 1024>>>(n);
    k_scatter<<<ge, B>>>(src, dst, e);

    // pipeline
    k_pre<<<1, 64>>>(encW, encb, g1W);
    k_enc_gat1<<<gn, B>>>(x, g1as, g1ad, n);
    k_msg1<<<gw, B>>>(n);
    k_fin1_gat2<<<gn, B>>>(g1b, g2W, g2as, g2ad, n);
    k_msg2<<<gw, B>>>(n);
    k_fin2_heads<<<gn, B>>>(g2b, eoW1, eob1, noW1, nob1, noW2, nob2, out, n, e);
    k_edgehead<<<gw, B>>>(eattr, eoW1, eoW2, eob2, out, n);
}